// round 8
// baseline (speedup 1.0000x reference)
#include <cuda_runtime.h>
#include <cstdint>

// ---------------------------------------------------------------------------
// Problem constants
//   B=8, C_IN=256, DIM=64, HEADS=8, D_IN=128, DKQ=8, DV=16, QKV=32
//   N = B*DIM*DIM = 32768 "pixels"; sequences: 512 of length 64
// ---------------------------------------------------------------------------
#define NT 32768
#define EPSV 1e-5f

__device__ float  g_y1[128 * NT];      // conv-in raw output, layout [c][b][w][h]
__device__ float  g_qkv[256 * NT];     // qkv, layout [o][bw][pos]
__device__ float  g_outatt[256 * NT];  // attention out (sve ch 0..127, sv 128..255)
__device__ float  g_x3[128 * NT];      // att1 combined (input to qkv2 GEMM)
__device__ float  g_y2[256 * NT];      // conv-out raw output [o][n1]
// stats offsets: convin @0(256) att1 @256(48) out1 @304(512) att2 @816(48)
//                out2 @864(512) convout @1376(512)
__device__ double g_st[1888];
__device__ float  g_sb[1888];

// Pre-converted weight matrices, fragment-major tf32 hi/lo
//   mat0 w_in (128x256) @0, mat1 wqkv_h (256x128) @32768,
//   mat2 wqkv_w @65536, mat3 w_out @98304
__device__ float g_Ah[131072], g_Al[131072];

// Precomputed rel-embedding tables, double-buffered per direction
__device__ float g_Tq[2][8 * 64], g_Tk[2][8 * 64];
__device__ float g_Sq[2][36 * 64], g_Sk[2][36 * 64];

__device__ const int c_pi[36] = {0,0,0,0,0,0,0,0, 1,1,1,1,1,1,1, 2,2,2,2,2,2,
                                 3,3,3,3,3, 4,4,4,4, 5,5,5, 6,6, 7};
__device__ const int c_pj[36] = {0,1,2,3,4,5,6,7, 1,2,3,4,5,6,7, 2,3,4,5,6,7,
                                 3,4,5,6,7, 4,5,6,7, 5,6,7, 6,7, 7};

__global__ void zero_stats() {
    int i = blockIdx.x * 256 + threadIdx.x;
    if (i < 1888) g_st[i] = 0.0;
}

__global__ void make_scale(int stoff, const float* __restrict__ gamma,
                           const float* __restrict__ beta, int sboff, int C, float invN) {
    int t = blockIdx.x * 64 + threadIdx.x;
    if (t >= C) return;
    double mean = g_st[stoff + t] * (double)invN;
    double var  = g_st[stoff + C + t] * (double)invN - mean * mean;
    float s = gamma[t] * rsqrtf((float)var + EPSV);
    g_sb[sboff + t]     = s;
    g_sb[sboff + C + t] = beta[t] - (float)mean * s;
}

// ---------------------------------------------------------------------------
// 3xTF32 helpers
// ---------------------------------------------------------------------------
__device__ __forceinline__ void split_tf32(float x, float& hi, float& lo) {
    uint32_t h;
    asm("cvt.rna.tf32.f32 %0, %1;" : "=r"(h) : "f"(x));
    float hf = __uint_as_float(h);
    uint32_t l;
    asm("cvt.rna.tf32.f32 %0, %1;" : "=r"(l) : "f"(x - hf));
    hi = hf;
    lo = __uint_as_float(l);
}

#define MMA_TF32(c, a0, a1, a2, a3, b0, b1)                                    \
    asm volatile(                                                              \
        "mma.sync.aligned.m16n8k8.row.col.f32.tf32.tf32.f32 "                  \
        "{%0,%1,%2,%3}, {%4,%5,%6,%7}, {%8,%9}, {%0,%1,%2,%3};"                \
        : "+f"(c[0]), "+f"(c[1]), "+f"(c[2]), "+f"(c[3])                       \
        : "r"(a0), "r"(a1), "r"(a2), "r"(a3), "r"(b0), "r"(b1))

// ---------------------------------------------------------------------------
// prep_A4: convert the 4 weight matrices to fragment-major tf32 hi/lo once.
//   A frag (16m x 8k): word = frag*128 + ((m&7)*4+(k&3))*4 + rg
//   frag = (k>>3)*(M>>4) + (m>>4);  rg = ((k>>2)&1)*2 + ((m>>3)&1)
// ---------------------------------------------------------------------------
__global__ void __launch_bounds__(256) prep_A4(const float* __restrict__ w_in,
                                               const float* __restrict__ wqkv_h,
                                               const float* __restrict__ wqkv_w,
                                               const float* __restrict__ w_out) {
    int idx = blockIdx.x * 256 + threadIdx.x;   // 0..131071
    int mat = idx >> 15;
    int e = idx & 32767;
    const float* src = (mat == 0) ? w_in : (mat == 1) ? wqkv_h
                      : (mat == 2) ? wqkv_w : w_out;
    int M, K, m, k;
    if (mat == 0) { M = 128; K = 256; m = e >> 8; k = e & 255; }
    else          { M = 256; K = 128; m = e >> 7; k = e & 127; }
    float h, l;
    split_tf32(src[e], h, l);
    int frag = (k >> 3) * (M >> 4) + (m >> 4);
    int rg = ((k >> 2) & 1) * 2 + ((m >> 3) & 1);
    int word = (mat << 15) + frag * 128 + ((m & 7) * 4 + (k & 3)) * 4 + rg;
    g_Ah[word] = h;
    g_Al[word] = l;
}

// ---------------------------------------------------------------------------
// GEMM via 3xTF32 mma.sync.
//   A: linear copy of pre-converted fragments (LDG.128 -> STS.128, cf).
//   B: hi/lo interleaved frags: word = frag*132 + ((n&7)*4+(k&3))*4
//        + ((k>>2)&1)*2 + {0=h,1=l};  compute LDS.128 -> (bh0,bl0,bh1,bl1).
// MODE 0 conv-in (gather x_in, scatter y1 + stats), 1 qkv (BN+relu at load),
// 2 qkv plain (reads x3), 3 conv-out (fused combine2 at load, +stats).
// Block tile 128x128, k-chunk 16; 8 warps (64m x 32n each); 2 CTA/SM.
// ---------------------------------------------------------------------------
template <int MODE>
__device__ __forceinline__ float4 gemm_loadB(const float* __restrict__ Bext,
                                             int n0, int k, int nn) {
    if (MODE == 0) {
        return *(const float4*)&Bext[(n0 >> 12) * 1048576 + k * 4096 + (n0 & 4095) + nn];
    } else if (MODE == 3) {
        float4 a = *(const float4*)&g_outatt[k * NT + n0 + nn];
        float4 b = *(const float4*)&g_outatt[(128 + k) * NT + n0 + nn];
        float sA = g_sb[864 + k],       bA = g_sb[864 + 256 + k];
        float sB = g_sb[864 + 128 + k], bB = g_sb[864 + 256 + 128 + k];
        float4 v;
        v.x = fmaxf(a.x * sA + bA + b.x * sB + bB, 0.f);
        v.y = fmaxf(a.y * sA + bA + b.y * sB + bB, 0.f);
        v.z = fmaxf(a.z * sA + bA + b.z * sB + bB, 0.f);
        v.w = fmaxf(a.w * sA + bA + b.w * sB + bB, 0.f);
        return v;
    } else {
        const float* Bp = (MODE == 1) ? g_y1 : g_x3;
        float4 v = *(const float4*)&Bp[k * NT + n0 + nn];
        if (MODE == 1) {
            float s = g_sb[k], bi = g_sb[128 + k];
            v.x = fmaxf(fmaf(v.x, s, bi), 0.f);
            v.y = fmaxf(fmaf(v.y, s, bi), 0.f);
            v.z = fmaxf(fmaf(v.z, s, bi), 0.f);
            v.w = fmaxf(fmaf(v.w, s, bi), 0.f);
        }
        return v;
    }
}

template <int MODE>
__global__ void __launch_bounds__(256, 2) gemm_k(const float* __restrict__ Bext, int K) {
    constexpr int M    = (MODE == 0) ? 128 : 256;
    constexpr int WOFF = (MODE == 0) ? 0 : ((MODE == 1) ? 32768
                        : ((MODE == 2) ? 65536 : 98304));
    constexpr int KFR  = M >> 4;               // frags per k-group
    __shared__ float Ash[2048], Asl[2048];     // 16 frags * 128
    __shared__ float Bsi[4224];                // 32 frags * 132 (hi/lo interleaved)
    __shared__ float ssum[128], ssq[128];
    const int n0 = blockIdx.x * 128;
    const int m0 = blockIdx.y * 128;
    const int tid = threadIdx.x;
    const int warp = tid >> 5, lane = tid & 31;
    const int lq = lane & 3, lr = lane >> 2;
    const int mb = (warp & 1) * 64;
    const int nb = (warp >> 1) * 32;

    float* Cp = (MODE == 0) ? g_y1 : ((MODE == 3) ? g_y2 : g_qkv);

    // A copy coords
    const int asf = tid >> 5;                   // sfrag for r=0 (0..7), +8 for r=1
    const int aof = (tid & 31) * 4;             // word offset within frag
    // B staging coords
    const int bn4 = (tid & 31) * 4;
    const int bst = (bn4 >> 3) * 132 + ((bn4 & 7) * 4 + (warp & 3)) * 4
                  + ((warp >> 2) & 1) * 2;      // + r*16*132 per round

    float acc[4][4][4];
#pragma unroll
    for (int mt = 0; mt < 4; mt++)
#pragma unroll
        for (int nt = 0; nt < 4; nt++)
#pragma unroll
            for (int c = 0; c < 4; c++) acc[mt][nt][c] = 0.f;

    const int nchunk = K >> 4;
    for (int c0 = 0; c0 < nchunk; c0++) {
        const int k0 = c0 * 16;
        // ---- A: linear copy of pre-converted fragments ----
#pragma unroll
        for (int r = 0; r < 2; r++) {
            int sfrag = asf + r * 8;
            int kgrp = sfrag >> 3, mloc = sfrag & 7;
            int gw = WOFF + ((c0 * 2 + kgrp) * KFR + (m0 >> 4) + mloc) * 128 + aof;
            *(float4*)&Ash[sfrag * 128 + aof] = *(const float4*)&g_Ah[gw];
            *(float4*)&Asl[sfrag * 128 + aof] = *(const float4*)&g_Al[gw];
        }
        // ---- B: load, split, store interleaved ----
#pragma unroll
        for (int r = 0; r < 2; r++) {
            int kr = warp + r * 8;
            float4 v = gemm_loadB<MODE>(Bext, n0, k0 + kr, bn4);
            int base = r * 16 * 132 + bst;
            float h, l;
            split_tf32(v.x, h, l); *(float2*)&Bsi[base +  0] = make_float2(h, l);
            split_tf32(v.y, h, l); *(float2*)&Bsi[base + 16] = make_float2(h, l);
            split_tf32(v.z, h, l); *(float2*)&Bsi[base + 32] = make_float2(h, l);
            split_tf32(v.w, h, l); *(float2*)&Bsi[base + 48] = make_float2(h, l);
        }
        __syncthreads();

        // ---- compute ----
#pragma unroll
        for (int ks = 0; ks < 2; ks++) {
            float4 bf[4];
#pragma unroll
            for (int nt = 0; nt < 4; nt++)
                bf[nt] = *(const float4*)&Bsi[(ks * 16 + (nb >> 3) + nt) * 132 + lane * 4];
#pragma unroll
            for (int mt = 0; mt < 4; mt++) {
                int aa = (ks * 8 + (mb >> 4) + mt) * 128 + lane * 4;
                float4 ha = *(const float4*)&Ash[aa];
                float4 la = *(const float4*)&Asl[aa];
                uint32_t ah0 = __float_as_uint(ha.x), ah1 = __float_as_uint(ha.y);
                uint32_t ah2 = __float_as_uint(ha.z), ah3 = __float_as_uint(ha.w);
                uint32_t al0 = __float_as_uint(la.x), al1 = __float_as_uint(la.y);
                uint32_t al2 = __float_as_uint(la.z), al3 = __float_as_uint(la.w);
#pragma unroll
                for (int nt = 0; nt < 4; nt++) {
                    uint32_t bh0 = __float_as_uint(bf[nt].x);
                    uint32_t bl0 = __float_as_uint(bf[nt].y);
                    uint32_t bh1 = __float_as_uint(bf[nt].z);
                    uint32_t bl1 = __float_as_uint(bf[nt].w);
                    MMA_TF32(acc[mt][nt], ah0, ah1, ah2, ah3, bh0, bh1);
                    MMA_TF32(acc[mt][nt], al0, al1, al2, al3, bh0, bh1);
                    MMA_TF32(acc[mt][nt], ah0, ah1, ah2, ah3, bl0, bl1);
                }
            }
        }
        __syncthreads();
    }

    if (MODE == 0 || MODE == 3) {
        for (int t = tid; t < 128; t += 256) { ssum[t] = 0.f; ssq[t] = 0.f; }
        __syncthreads();
    }

    const int lqe = lane & 3, lre = lane >> 2;
    if (MODE == 0) {
        const int bb = n0 >> 12, hw0 = n0 & 4095;
#pragma unroll
        for (int mt = 0; mt < 4; mt++) {
#pragma unroll
            for (int half = 0; half < 2; half++) {
                int o = mb + mt * 16 + lre + half * 8;  // m0 == 0
                float rs = 0.f, rq = 0.f;
#pragma unroll
                for (int nt = 0; nt < 4; nt++) {
#pragma unroll
                    for (int cc = 0; cc < 2; cc++) {
                        int hw = hw0 + nb + nt * 8 + 2 * lqe + cc;
                        float v = acc[mt][nt][half * 2 + cc];
                        Cp[o * NT + bb * 4096 + (hw & 63) * 64 + (hw >> 6)] = v;
                        rs += v; rq += v * v;
                    }
                }
                atomicAdd(&ssum[o], rs);
                atomicAdd(&ssq[o], rq);
            }
        }
    } else {
#pragma unroll
        for (int mt = 0; mt < 4; mt++) {
#pragma unroll
            for (int half = 0; half < 2; half++) {
                int o = m0 + mb + mt * 16 + lre + half * 8;
                float rs = 0.f, rq = 0.f;
#pragma unroll
                for (int nt = 0; nt < 4; nt++) {
                    float2 v2 = make_float2(acc[mt][nt][half * 2], acc[mt][nt][half * 2 + 1]);
                    *(float2*)&Cp[o * NT + n0 + nb + nt * 8 + 2 * lqe] = v2;
                    if (MODE == 3) { rs += v2.x + v2.y; rq += v2.x * v2.x + v2.y * v2.y; }
                }
                if (MODE == 3) {
                    atomicAdd(&ssum[o - m0], rs);
                    atomicAdd(&ssq[o - m0], rq);
                }
            }
        }
    }

    if (MODE == 0 || MODE == 3) {
        __syncthreads();
        const int base = (MODE == 0) ? 0 : 1376;
        const int Csz  = (MODE == 0) ? 128 : 256;
        if (tid < 128) {
            atomicAdd(&g_st[base + m0 + tid], (double)ssum[tid]);
            atomicAdd(&g_st[base + Csz + m0 + tid], (double)ssq[tid]);
        }
    }
}

// ---------------------------------------------------------------------------
// prep_S: precompute sliding-window tables of the rel embedding.
// grid (12, 2): blockIdx.y selects direction (0=h, 1=w).
// ---------------------------------------------------------------------------
__global__ void __launch_bounds__(256) prep_S(const float* __restrict__ rel_h,
                                              const float* __restrict__ rel_w) {
    const int dir = blockIdx.y;
    const float* rel = dir ? rel_w : rel_h;
    __shared__ float r[16][127];
    for (int t = threadIdx.x; t < 16 * 127; t += 256) r[t / 127][t % 127] = rel[t];
    __syncthreads();
    const int g0 = blockIdx.x * 256 + threadIdx.x;
    const int gs = gridDim.x * 256;
    for (int t = g0; t < 1024; t += gs) {
        int which = t >> 9, i = (t >> 6) & 7, d = t & 63;
        const float* rr = r[which * 8 + i];
        float s = 0.f;
        for (int u = 0; u < 64; u++) s += rr[d + u];
        (which ? g_Tk[dir] : g_Tq[dir])[i * 64 + d] = s;
    }
    for (int t = g0; t < 4608; t += gs) {
        int which = t / 2304, rem = t % 2304, p = rem >> 6, d = rem & 63;
        const float* a = r[which * 8 + c_pi[p]];
        const float* b = r[which * 8 + c_pj[p]];
        float s = 0.f;
        for (int u = 0; u < 64; u++) s = fmaf(a[d + u], b[d + u], s);
        (which ? g_Sk[dir] : g_Sq[dir])[p * 64 + d] = s;
    }
}

// ---------------------------------------------------------------------------
// att_stats: BN statistics of qr/kr/dots without materializing logits.
// ---------------------------------------------------------------------------
__global__ void __launch_bounds__(256) att_stats(int stoff, int dir) {
    const int bw = blockIdx.x, tid = threadIdx.x;
    __shared__ float qT[8][512];   // [h][d*8 + i]
    __shared__ float kT[8][512];
    __shared__ float rsq[8][8], rsk[8][8], tqs[8][8], tks[8][8];

    for (int t = tid; t < 8192; t += 256) {
        int which = t >> 12, o = (t >> 6) & 63, d = t & 63;
        float v = g_qkv[(which * 64 + o) * NT + bw * 64 + d];
        int h = o & 7, i = o >> 3;
        if (which == 0) qT[h][d * 8 + i] = v; else kT[h][d * 8 + i] = v;
    }
    __syncthreads();

    const int h = tid >> 5, lane = tid & 31;
    const float* Tq = g_Tq[dir];
    const float* Tk = g_Tk[dir];
    const float* Sq = g_Sq[dir];
    const float* Sk = g_Sk[dir];
    if (lane < 8) {
        float s = 0.f;
        for (int d = 0; d < 64; d++) s += qT[h][d * 8 + lane];
        rsq[h][lane] = s;
    } else if (lane < 16) {
        int i = lane - 8; float s = 0.f;
        for (int d = 0; d < 64; d++) s += kT[h][d * 8 + i];
        rsk[h][i] = s;
    } else if (lane < 24) {
        int i = lane - 16; float s = 0.f;
        for (int d = 0; d < 64; d++) s = fmaf(qT[h][d * 8 + i], __ldg(&Tq[i * 64 + d]), s);
        tqs[h][i] = s;
    } else {
        int i = lane - 24; float s = 0.f;
        for (int d = 0; d < 64; d++) s = fmaf(kT[h][d * 8 + i], __ldg(&Tk[i * 64 + d]), s);
        tks[h][i] = s;
    }

    float dsq = 0.f, wq = 0.f, wk = 0.f;
    for (int p = lane; p < 36; p += 32) {
        int i = c_pi[p], i2 = c_pj[p];
        float m = (i == i2) ? 1.f : 2.f;
        float gq = 0.f, wqp = 0.f, gk = 0.f, wkp = 0.f;
        for (int d = 0; d < 64; d++) {
            float pq = qT[h][d * 8 + i] * qT[h][d * 8 + i2];
            gq += pq; wqp = fmaf(pq, __ldg(&Sq[p * 64 + d]), wqp);
            float pk = kT[h][d * 8 + i] * kT[h][d * 8 + i2];
            gk += pk; wkp = fmaf(pk, __ldg(&Sk[p * 64 + d]), wkp);
        }
        dsq = fmaf(m * gq, gk, dsq); wq = fmaf(m, wqp, wq); wk = fmaf(m, wkp, wk);
    }
#pragma unroll
    for (int off = 16; off; off >>= 1) {
        dsq += __shfl_xor_sync(~0u, dsq, off);
        wq  += __shfl_xor_sync(~0u, wq,  off);
        wk  += __shfl_xor_sync(~0u, wk,  off);
    }
    __syncwarp();
    if (lane == 0) {
        float ds = 0.f, qs = 0.f, ks = 0.f;
#pragma unroll
        for (int i = 0; i < 8; i++) {
            ds = fmaf(rsq[h][i], rsk[h][i], ds);
            qs += tqs[h][i]; ks += tks[h][i];
        }
        atomicAdd(&g_st[stoff + h * 3 + 0], (double)qs);
        atomicAdd(&g_st[stoff + h * 3 + 1], (double)ks);
        atomicAdd(&g_st[stoff + h * 3 + 2], (double)ds);
        atomicAdd(&g_st[stoff + 24 + h * 3 + 0], (double)wq);
        atomicAdd(&g_st[stoff + 24 + h * 3 + 1], (double)wk);
        atomicAdd(&g_st[stoff + 24 + h * 3 + 2], (double)dsq);
    }
}

// ---------------------------------------------------------------------------
// att_pass2: logits (BN applied) -> softmax -> sv & sve.  Conflict-free:
// Phase A: warp = 8 d-rows, lane = j (stride-1 rel reads, broadcast q/k).
// Phase B: warp = 2 i-channels, lane = d (stride-1 rel, pitch-65 sat).
// ---------------------------------------------------------------------------
__global__ void __launch_bounds__(256) att_pass2(const float* __restrict__ rel,
                                                 int sba, int sto) {
    const int bw = blockIdx.x, h = blockIdx.y, tid = threadIdx.x;
    const int warp = tid >> 5, lane = tid & 31;
    __shared__ float sq[8][65], sk[8][65], svv[16][65];
    __shared__ float srel[32][129];
    __shared__ float sat[64][65];

#pragma unroll
    for (int r = 0; r < 8; r++) {
        int t = tid + r * 256;
        int o = t >> 6, d = t & 63;
        float v = g_qkv[(o * 8 + h) * NT + bw * 64 + d];
        if (o < 8) sq[o][d] = v;
        else if (o < 16) sk[o - 8][d] = v;
        else svv[o - 16][d] = v;
    }
    for (int t = tid; t < 32 * 127; t += 256) srel[t / 127][t % 127] = rel[t];
    const float s0 = g_sb[sba + h * 3], s1v = g_sb[sba + h * 3 + 1], s2v = g_sb[sba + h * 3 + 2];
    const float bsum = g_sb[sba + 24 + h * 3] + g_sb[sba + 24 + h * 3 + 1]
                     + g_sb[sba + 24 + h * 3 + 2];
    __syncthreads();

    {   // ---- Phase A: logits + softmax.  j0 = lane, j1 = lane + 32. ----
        float kk0[8], kk1[8];
#pragma unroll
        for (int i = 0; i < 8; i++) {
            kk0[i] = sk[i][lane];
            kk1[i] = sk[i][lane + 32];
        }
        const int dbase = warp * 8;
#pragma unroll
        for (int r = 0; r < 8; r++) {
            const int d = dbase + r;
            const int m0 = d - lane + 63;   // in [32,126]; m0-32 in [0,94]
            float qr0 = 0, kr0 = 0, dt0 = 0, qr1 = 0, kr1 = 0, dt1 = 0;
#pragma unroll
            for (int i = 0; i < 8; i++) {
                float qi  = sq[i][d];       // broadcast
                float kdi = sk[i][d];       // broadcast
                float rq0 = srel[i][m0],     rq1 = srel[i][m0 - 32];
                float rk0 = srel[8 + i][m0], rk1 = srel[8 + i][m0 - 32];
                qr0 = fmaf(qi, rq0, qr0);   qr1 = fmaf(qi, rq1, qr1);
                kr0 = fmaf(kdi, rk0, kr0);  kr1 = fmaf(kdi, rk1, kr1);
                dt0 = fmaf(qi, kk0[i], dt0); dt1 = fmaf(qi, kk1[i], dt1);
            }
            float l0 = qr0 * s0 + kr0 * s1v + dt0 * s2v + bsum;
            float l1 = qr1 * s0 + kr1 * s1v + dt1 * s2v + bsum;
            float mx = fmaxf(l0, l1);
#pragma unroll
            for (int off = 16; off; off >>= 1)
                mx = fmaxf(mx, __shfl_xor_sync(~0u, mx, off));
            float e0 = __expf(l0 - mx), e1 = __expf(l1 - mx);
            float se = e0 + e1;
#pragma unroll
            for (int off = 16; off; off >>= 1)
                se += __shfl_xor_sync(~0u, se, off);
            float inv = 1.f / se;
            sat[d][lane]      = e0 * inv;
            sat[d][lane + 32] = e1 * inv;
        }
    }
    __syncthreads();

    {   // ---- Phase B: sv & sve.  i0 = 2*warp, i1 = i0+1; da = lane, db = lane+32.
        const int i0 = warp * 2, i1 = i0 + 1;
        const int da = lane, db = lane + 32;
        float av0a = 0, av0b = 0, av1a = 0, av1b = 0;
        float ae0a = 0, ae0b = 0, ae1a = 0, ae1b = 0;
        const float* r0 = &srel[16 + i0][0];
        const float* r1 = &srel[16 + i1][0];
#pragma unroll 4
        for (int j = 0; j < 64; j++) {
            float Aa = sat[da][j];          // stride 65 across lanes: cf
            float Ab = sat[db][j];
            float v0 = svv[i0][j], v1 = svv[i1][j];   // broadcast
            float r0a = r0[da - j + 63], r0b = r0[db - j + 63];
            float r1a = r1[da - j + 63], r1b = r1[db - j + 63];
            av0a = fmaf(Aa, v0, av0a);  av0b = fmaf(Ab, v0, av0b);
            av1a = fmaf(Aa, v1, av1a);  av1b = fmaf(Ab, v1, av1b);
            ae0a = fmaf(Aa, r0a, ae0a); ae0b = fmaf(Ab, r0b, ae0b);
            ae1a = fmaf(Aa, r1a, ae1a); ae1b = fmaf(Ab, r1b, ae1b);
        }
        const int ch0 = h * 16 + i0, ch1 = h * 16 + i1;
        g_outatt[ch0 * NT + bw * 64 + da] = ae0a;
        g_outatt[ch0 * NT + bw * 64 + db] = ae0b;
        g_outatt[ch1 * NT + bw * 64 + da] = ae1a;
        g_outatt[ch1 * NT + bw * 64 + db] = ae1b;
        g_outatt[(128 + ch0) * NT + bw * 64 + da] = av0a;
        g_outatt[(128 + ch0) * NT + bw * 64 + db] = av0b;
        g_outatt[(128 + ch1) * NT + bw * 64 + da] = av1a;
        g_outatt[(128 + ch1) * NT + bw * 64 + db] = av1b;

        float se0 = ae0a + ae0b, qe0 = ae0a * ae0a + ae0b * ae0b;
        float se1 = ae1a + ae1b, qe1 = ae1a * ae1a + ae1b * ae1b;
        float sv0 = av0a + av0b, qv0 = av0a * av0a + av0b * av0b;
        float sv1 = av1a + av1b, qv1 = av1a * av1a + av1b * av1b;
#pragma unroll
        for (int off = 16; off; off >>= 1) {
            se0 += __shfl_xor_sync(~0u, se0, off); qe0 += __shfl_xor_sync(~0u, qe0, off);
            se1 += __shfl_xor_sync(~0u, se1, off); qe1 += __shfl_xor_sync(~0u, qe1, off);
            sv0 += __shfl_xor_sync(~0u, sv0, off); qv0 += __shfl_xor_sync(~0u, qv0, off);
            sv1 += __shfl_xor_sync(~0u, sv1, off); qv1 += __shfl_xor_sync(~0u, qv1, off);
        }
        if (lane == 0) {
            atomicAdd(&g_st[sto + ch0], (double)se0);
            atomicAdd(&g_st[sto + ch1], (double)se1);
            atomicAdd(&g_st[sto + 256 + ch0], (double)qe0);
            atomicAdd(&g_st[sto + 256 + ch1], (double)qe1);
            atomicAdd(&g_st[sto + 128 + ch0], (double)sv0);
            atomicAdd(&g_st[sto + 128 + ch1], (double)sv1);
            atomicAdd(&g_st[sto + 256 + 128 + ch0], (double)qv0);
            atomicAdd(&g_st[sto + 256 + 128 + ch1], (double)qv1);
        }
    }
}

// combine att1: x3[c][b][h][w] = bn(sve) + bn(sv), with h<->w transpose
__global__ void __launch_bounds__(256) combine1() {
    const int c = blockIdx.x, b = blockIdx.y, tid = threadIdx.x;
    __shared__ float tile[64][65];
    const float sA = g_sb[304 + c],        bA = g_sb[304 + 256 + c];
    const float sB = g_sb[304 + c + 128],  bB = g_sb[304 + 256 + c + 128];
    const float* pA = g_outatt + c * NT + b * 4096;
    const float* pB = g_outatt + (c + 128) * NT + b * 4096;
    for (int t = tid; t < 4096; t += 256)
        tile[t >> 6][t & 63] = pA[t] * sA + bA + pB[t] * sB + bB;
    __syncthreads();
    float* q = g_x3 + c * NT + b * 4096;
    for (int t = tid; t < 4096; t += 256)
        q[t] = tile[t & 63][t >> 6];
}

// final: out = relu(bn(conv_out) + x_in)
__global__ void __launch_bounds__(256) final_k(const float* __restrict__ x_in,
                                               float* __restrict__ out) {
    int idx = blockIdx.x * 256 + threadIdx.x;
    int o = idx >> 15, m = idx & (NT - 1);
    int b = m >> 12, hw = m & 4095;
    float v = g_y2[idx] * g_sb[1376 + o] + g_sb[1376 + 256 + o];
    int oidx = (b * 256 + o) * 4096 + hw;
    v += x_in[oidx];
    out[oidx] = fmaxf(v, 0.f);
}

// ---------------------------------------------------------------------------
extern "C" void kernel_launch(void* const* d_in, const int* in_sizes, int n_in,
                              void* d_out, int out_size) {
    (void)in_sizes; (void)n_in; (void)out_size;
    const float* x_in   = (const float*)d_in[0];
    const float* w_in   = (const float*)d_in[1];
    const float* g_in   = (const float*)d_in[2];
    const float* b_in   = (const float*)d_in[3];
    const float* w_out  = (const float*)d_in[4];
    const float* g_out  = (const float*)d_in[5];
    const float* b_out  = (const float*)d_in[6];
    const float* wqkv_h = (const float*)d_in[7];
    const float* rel_h  = (const float*)d_in[8];
    const float* ga_h   = (const float*)d_in[9];
    const float* ba_h   = (const float*)d_in[10];
    const float* go_h   = (const float*)d_in[11];
    const float* bo_h   = (const float*)d_in[12];
    const float* wqkv_w = (const float*)d_in[13];
    const float* rel_w  = (const float*)d_in[14];
    const float* ga_w   = (const float*)d_in[15];
    const float* ba_w   = (const float*)d_in[16];
    const float* go_w   = (const float*)d_in[17];
    const float* bo_w   = (const float*)d_in[18];

    zero_stats<<<8, 256>>>();                                   // 0
    prep_S<<<dim3(12, 2), 256>>>(rel_h, rel_w);                 // 1
    prep_A4<<<512, 256>>>(w_in, wqkv_h, wqkv_w, w_out);         // 2

    // conv-in (+stats) -> y1                                   // 3 (profiled)
    gemm_k<0><<<dim3(256, 1), 256>>>(x_in, 256);
    make_scale<<<2, 64>>>(0, g_in, b_in, 0, 128, 1.f / 32768.f);

    // --- axial attention along H ---
    gemm_k<1><<<dim3(256, 2), 256>>>(nullptr, 128);
    att_stats<<<512, 256>>>(256, 0);
    make_scale<<<1, 64>>>(256, ga_h, ba_h, 256, 24, 1.f / 2097152.f);
    att_pass2<<<dim3(512, 8), 256>>>(rel_h, 256, 304);
    make_scale<<<4, 64>>>(304, go_h, bo_h, 304, 256, 1.f / 32768.f);
    combine1<<<dim3(128, 8), 256>>>();

    // --- axial attention along W ---
    gemm_k<2><<<dim3(256, 2), 256>>>(nullptr, 128);
    att_stats<<<512, 256>>>(816, 1);
    make_scale<<<1, 64>>>(816, ga_w, ba_w, 816, 24, 1.f / 2097152.f);
    att_pass2<<<dim3(512, 8), 256>>>(rel_w, 816, 864);
    make_scale<<<4, 64>>>(864, go_w, bo_w, 864, 256, 1.f / 32768.f);

    // conv-out (fused combine2 at load, +stats) -> y2
    gemm_k<3><<<dim3(256, 2), 256>>>(nullptr, 128);
    make_scale<<<4, 64>>>(1376, g_out, b_out, 1376, 256, 1.f / 32768.f);

    final_k<<<32768, 256>>>(x_in, (float*)d_out);
}

// round 10
// speedup vs baseline: 1.0176x; 1.0176x over previous
#include <cuda_runtime.h>
#include <cstdint>

// ---------------------------------------------------------------------------
// Problem constants
//   B=8, C_IN=256, DIM=64, HEADS=8, D_IN=128, DKQ=8, DV=16, QKV=32
//   N = B*DIM*DIM = 32768 "pixels"; sequences: 512 of length 64
// ---------------------------------------------------------------------------
#define NT 32768
#define EPSV 1e-5f

__device__ float  g_y1[128 * NT];      // conv-in raw output, layout [c][b][w][h]
__device__ float  g_qkv[256 * NT];     // qkv, layout [o][bw][pos]
__device__ float  g_outatt[256 * NT];  // attention out (sve ch 0..127, sv 128..255)
__device__ float  g_x3[128 * NT];      // att1 combined (input to qkv2 GEMM)
__device__ float  g_y2[256 * NT];      // conv-out raw output [o][n1]
// stats offsets: convin @0(256) att1 @256(48) out1 @304(512) att2 @816(48)
//                out2 @864(512) convout @1376(512)
__device__ double g_st[1888];
__device__ float  g_sb[1888];

// Pre-converted weight matrices, fragment-major tf32 hi/lo
//   mat0 w_in (128x256) @0, mat1 wqkv_h (256x128) @32768,
//   mat2 wqkv_w @65536, mat3 w_out @98304
__device__ float g_Ah[131072], g_Al[131072];

// Precomputed rel-embedding tables, double-buffered per direction
__device__ float g_Tq[2][8 * 64], g_Tk[2][8 * 64];
__device__ float g_Sq[2][36 * 64], g_Sk[2][36 * 64];

__device__ const int c_pi[36] = {0,0,0,0,0,0,0,0, 1,1,1,1,1,1,1, 2,2,2,2,2,2,
                                 3,3,3,3,3, 4,4,4,4, 5,5,5, 6,6, 7};
__device__ const int c_pj[36] = {0,1,2,3,4,5,6,7, 1,2,3,4,5,6,7, 2,3,4,5,6,7,
                                 3,4,5,6,7, 4,5,6,7, 5,6,7, 6,7, 7};

__global__ void zero_stats() {
    int i = blockIdx.x * 256 + threadIdx.x;
    if (i < 1888) g_st[i] = 0.0;
}

__global__ void make_scale(int stoff, const float* __restrict__ gamma,
                           const float* __restrict__ beta, int sboff, int C, float invN) {
    int t = blockIdx.x * 64 + threadIdx.x;
    if (t >= C) return;
    double mean = g_st[stoff + t] * (double)invN;
    double var  = g_st[stoff + C + t] * (double)invN - mean * mean;
    float s = gamma[t] * rsqrtf((float)var + EPSV);
    g_sb[sboff + t]     = s;
    g_sb[sboff + C + t] = beta[t] - (float)mean * s;
}

// ---------------------------------------------------------------------------
// 3xTF32 helpers
// ---------------------------------------------------------------------------
__device__ __forceinline__ void split_tf32(float x, float& hi, float& lo) {
    uint32_t h;
    asm("cvt.rna.tf32.f32 %0, %1;" : "=r"(h) : "f"(x));
    float hf = __uint_as_float(h);
    uint32_t l;
    asm("cvt.rna.tf32.f32 %0, %1;" : "=r"(l) : "f"(x - hf));
    hi = hf;
    lo = __uint_as_float(l);
}

#define MMA_TF32(c, a0, a1, a2, a3, b0, b1)                                    \
    asm volatile(                                                              \
        "mma.sync.aligned.m16n8k8.row.col.f32.tf32.tf32.f32 "                  \
        "{%0,%1,%2,%3}, {%4,%5,%6,%7}, {%8,%9}, {%0,%1,%2,%3};"                \
        : "+f"(c[0]), "+f"(c[1]), "+f"(c[2]), "+f"(c[3])                       \
        : "r"(a0), "r"(a1), "r"(a2), "r"(a3), "r"(b0), "r"(b1))

#define CP_ASYNC16(dst_u32, src_ptr)                                           \
    asm volatile("cp.async.cg.shared.global [%0], [%1], 16;"                   \
                 :: "r"(dst_u32), "l"(src_ptr))
#define CP_COMMIT()  asm volatile("cp.async.commit_group;")
#define CP_WAIT0()   asm volatile("cp.async.wait_group 0;" ::: "memory")

// ---------------------------------------------------------------------------
// prep_A4: convert the 4 weight matrices to fragment-major tf32 hi/lo once.
//   A frag (16m x 8k): word = frag*128 + ((m&7)*4+(k&3))*4 + rg
//   frag = (k>>3)*(M>>4) + (m>>4);  rg = ((k>>2)&1)*2 + ((m>>3)&1)
// ---------------------------------------------------------------------------
__global__ void __launch_bounds__(256) prep_A4(const float* __restrict__ w_in,
                                               const float* __restrict__ wqkv_h,
                                               const float* __restrict__ wqkv_w,
                                               const float* __restrict__ w_out) {
    int idx = blockIdx.x * 256 + threadIdx.x;   // 0..131071
    int mat = idx >> 15;
    int e = idx & 32767;
    const float* src = (mat == 0) ? w_in : (mat == 1) ? wqkv_h
                      : (mat == 2) ? wqkv_w : w_out;
    int M, m, k;
    if (mat == 0) { M = 128; m = e >> 8; k = e & 255; }
    else          { M = 256; m = e >> 7; k = e & 127; }
    float h, l;
    split_tf32(src[e], h, l);
    int frag = (k >> 3) * (M >> 4) + (m >> 4);
    int rg = ((k >> 2) & 1) * 2 + ((m >> 3) & 1);
    int word = (mat << 15) + frag * 128 + ((m & 7) * 4 + (k & 3)) * 4 + rg;
    g_Ah[word] = h;
    g_Al[word] = l;
}

// ---------------------------------------------------------------------------
// Pipelined GEMM via 3xTF32 mma.sync, double-buffered smem.
//   A: cp.async 16B copies of pre-converted fragments (no regs, no cvt).
//   B: prefetch to regs at top of iter (LDG overlapped by MMA compute),
//      split+STS into the NEXT stage after compute.
//   B smem layout (hi/lo interleaved): word = frag*132 +
//      ((n&7)*4+(k&3))*4 + ((k>>2)&1)*2 + {0=h,1=l}; compute: LDS.128.
// MODE 0 conv-in (gather x_in, scatter y1 + stats), 1 qkv (BN+relu at load),
// 2 qkv plain (reads x3), 3 conv-out (fused combine2 at load, +stats).
// Block tile 128x128, k-chunk 16; 8 warps (64m x 32n each); 2 CTA/SM.
// Dynamic smem: 2 stages x (A 4096 + B 4224) + 256 = 16896 floats = 67584 B.
// ---------------------------------------------------------------------------
#define GEMM_SMEM_BYTES (16896 * 4)

template <int MODE>
__device__ __forceinline__ float4 gemm_loadB(const float* __restrict__ Bext,
                                             int n0, int k, int nn) {
    if (MODE == 0) {
        return *(const float4*)&Bext[(n0 >> 12) * 1048576 + k * 4096 + (n0 & 4095) + nn];
    } else if (MODE == 3) {
        float4 a = *(const float4*)&g_outatt[k * NT + n0 + nn];
        float4 b = *(const float4*)&g_outatt[(128 + k) * NT + n0 + nn];
        float sA = g_sb[864 + k],       bA = g_sb[864 + 256 + k];
        float sB = g_sb[864 + 128 + k], bB = g_sb[864 + 256 + 128 + k];
        float4 v;
        v.x = fmaxf(a.x * sA + bA + b.x * sB + bB, 0.f);
        v.y = fmaxf(a.y * sA + bA + b.y * sB + bB, 0.f);
        v.z = fmaxf(a.z * sA + bA + b.z * sB + bB, 0.f);
        v.w = fmaxf(a.w * sA + bA + b.w * sB + bB, 0.f);
        return v;
    } else {
        const float* Bp = (MODE == 1) ? g_y1 : g_x3;
        float4 v = *(const float4*)&Bp[k * NT + n0 + nn];
        if (MODE == 1) {
            float s = g_sb[k], bi = g_sb[128 + k];
            v.x = fmaxf(fmaf(v.x, s, bi), 0.f);
            v.y = fmaxf(fmaf(v.y, s, bi), 0.f);
            v.z = fmaxf(fmaf(v.z, s, bi), 0.f);
            v.w = fmaxf(fmaf(v.w, s, bi), 0.f);
        }
        return v;
    }
}

template <int MODE>
__global__ void __launch_bounds__(256, 2) gemm_k(const float* __restrict__ Bext, int K) {
    constexpr int M    = (MODE == 0) ? 128 : 256;
    constexpr int WOFF = (MODE == 0) ? 0 : ((MODE == 1) ? 32768
                        : ((MODE == 2) ? 65536 : 98304));
    constexpr int KFR  = M >> 4;               // frags per k-group
    extern __shared__ float sm[];
    // stage s: A hi @ s*4096, A lo @ s*4096+2048; B @ 8192 + s*4224
    float* ssum = sm + 16640;
    float* ssq  = sm + 16768;
    const int n0 = blockIdx.x * 128;
    const int m0 = blockIdx.y * 128;
    const int tid = threadIdx.x;
    const int warp = tid >> 5, lane = tid & 31;
    const int mb = (warp & 1) * 64;
    const int nb = (warp >> 1) * 32;

    float* Cp = (MODE == 0) ? g_y1 : ((MODE == 3) ? g_y2 : g_qkv);

    // A copy coords
    const int asf = tid >> 5;                   // sfrag for r=0 (0..7), +8 for r=1
    const int aof = (tid & 31) * 4;
    // B staging coords
    const int bn4 = (tid & 31) * 4;
    const int bst = (bn4 >> 3) * 132 + ((bn4 & 7) * 4 + (warp & 3)) * 4
                  + ((warp >> 2) & 1) * 2;

    float acc[4][4][4];
#pragma unroll
    for (int mt = 0; mt < 4; mt++)
#pragma unroll
        for (int nt = 0; nt < 4; nt++)
#pragma unroll
            for (int c = 0; c < 4; c++) acc[mt][nt][c] = 0.f;

    float4 bR[2];

    // --- prologue: chunk 0 into stage 0 ---
#pragma unroll
    for (int r = 0; r < 2; r++)
        bR[r] = gemm_loadB<MODE>(Bext, n0, warp + r * 8, bn4);
#pragma unroll
    for (int r = 0; r < 2; r++) {
        int sfrag = asf + r * 8;
        int kgrp = sfrag >> 3, mloc = sfrag & 7;
        int gw = WOFF + (kgrp * KFR + (m0 >> 4) + mloc) * 128 + aof;
        uint32_t dh = (uint32_t)__cvta_generic_to_shared(&sm[sfrag * 128 + aof]);
        CP_ASYNC16(dh, &g_Ah[gw]);
        CP_ASYNC16(dh + 2048 * 4, &g_Al[gw]);
    }
    CP_COMMIT();
#pragma unroll
    for (int r = 0; r < 2; r++) {
        float* base = &sm[8192 + r * 16 * 132 + bst];
        float h, l;
        split_tf32(bR[r].x, h, l); *(float2*)&base[0]  = make_float2(h, l);
        split_tf32(bR[r].y, h, l); *(float2*)&base[16] = make_float2(h, l);
        split_tf32(bR[r].z, h, l); *(float2*)&base[32] = make_float2(h, l);
        split_tf32(bR[r].w, h, l); *(float2*)&base[48] = make_float2(h, l);
    }
    CP_WAIT0();
    __syncthreads();

    const int nchunk = K >> 4;
    for (int c0 = 0; c0 < nchunk; c0++) {
        const int cur = c0 & 1, nxt = cur ^ 1;
        const bool more = (c0 + 1 < nchunk);

        // ---- issue next chunk's loads early (overlap with compute) ----
        if (more) {
            const int k0n = (c0 + 1) * 16;
#pragma unroll
            for (int r = 0; r < 2; r++)
                bR[r] = gemm_loadB<MODE>(Bext, n0, k0n + warp + r * 8, bn4);
#pragma unroll
            for (int r = 0; r < 2; r++) {
                int sfrag = asf + r * 8;
                int kgrp = sfrag >> 3, mloc = sfrag & 7;
                int gw = WOFF + (((c0 + 1) * 2 + kgrp) * KFR + (m0 >> 4) + mloc) * 128 + aof;
                uint32_t dh = (uint32_t)__cvta_generic_to_shared(
                    &sm[nxt * 4096 + sfrag * 128 + aof]);
                CP_ASYNC16(dh, &g_Ah[gw]);
                CP_ASYNC16(dh + 2048 * 4, &g_Al[gw]);
            }
            CP_COMMIT();
        }

        // ---- compute from stage cur ----
        const float* Ash = sm + cur * 4096;
        const float* Asl = Ash + 2048;
        const float* Bsi = sm + 8192 + cur * 4224;
#pragma unroll
        for (int ks = 0; ks < 2; ks++) {
            float4 bf[4];
#pragma unroll
            for (int nt = 0; nt < 4; nt++)
                bf[nt] = *(const float4*)&Bsi[(ks * 16 + (nb >> 3) + nt) * 132 + lane * 4];
#pragma unroll
            for (int mt = 0; mt < 4; mt++) {
                int aa = (ks * 8 + (mb >> 4) + mt) * 128 + lane * 4;
                float4 ha = *(const float4*)&Ash[aa];
                float4 la = *(const float4*)&Asl[aa];
                uint32_t ah0 = __float_as_uint(ha.x), ah1 = __float_as_uint(ha.y);
                uint32_t ah2 = __float_as_uint(ha.z), ah3 = __float_as_uint(ha.w);
                uint32_t al0 = __float_as_uint(la.x), al1 = __float_as_uint(la.y);
                uint32_t al2 = __float_as_uint(la.z), al3 = __float_as_uint(la.w);
#pragma unroll
                for (int nt = 0; nt < 4; nt++) {
                    uint32_t bh0 = __float_as_uint(bf[nt].x);
                    uint32_t bl0 = __float_as_uint(bf[nt].y);
                    uint32_t bh1 = __float_as_uint(bf[nt].z);
                    uint32_t bl1 = __float_as_uint(bf[nt].w);
                    MMA_TF32(acc[mt][nt], ah0, ah1, ah2, ah3, bh0, bh1);
                    MMA_TF32(acc[mt][nt], al0, al1, al2, al3, bh0, bh1);
                    MMA_TF32(acc[mt][nt], ah0, ah1, ah2, ah3, bl0, bl1);
                }
            }
        }

        // ---- store next B stage, drain cp.async, sync ----
        if (more) {
#pragma unroll
            for (int r = 0; r < 2; r++) {
                float* base = &sm[8192 + nxt * 4224 + r * 16 * 132 + bst];
                float h, l;
                split_tf32(bR[r].x, h, l); *(float2*)&base[0]  = make_float2(h, l);
                split_tf32(bR[r].y, h, l); *(float2*)&base[16] = make_float2(h, l);
                split_tf32(bR[r].z, h, l); *(float2*)&base[32] = make_float2(h, l);
                split_tf32(bR[r].w, h, l); *(float2*)&base[48] = make_float2(h, l);
            }
            CP_WAIT0();
            __syncthreads();
        }
    }
    __syncthreads();

    if (MODE == 0 || MODE == 3) {
        for (int t = tid; t < 128; t += 256) { ssum[t] = 0.f; ssq[t] = 0.f; }
        __syncthreads();
    }

    const int lqe = lane & 3, lre = lane >> 2;
    if (MODE == 0) {
        const int bb = n0 >> 12, hw0 = n0 & 4095;
#pragma unroll
        for (int mt = 0; mt < 4; mt++) {
#pragma unroll
            for (int half = 0; half < 2; half++) {
                int o = mb + mt * 16 + lre + half * 8;  // m0 == 0
                float rs = 0.f, rq = 0.f;
#pragma unroll
                for (int nt = 0; nt < 4; nt++) {
#pragma unroll
                    for (int cc = 0; cc < 2; cc++) {
                        int hw = hw0 + nb + nt * 8 + 2 * lqe + cc;
                        float v = acc[mt][nt][half * 2 + cc];
                        Cp[o * NT + bb * 4096 + (hw & 63) * 64 + (hw >> 6)] = v;
                        rs += v; rq += v * v;
                    }
                }
                atomicAdd(&ssum[o], rs);
                atomicAdd(&ssq[o], rq);
            }
        }
    } else {
#pragma unroll
        for (int mt = 0; mt < 4; mt++) {
#pragma unroll
            for (int half = 0; half < 2; half++) {
                int o = m0 + mb + mt * 16 + lre + half * 8;
                float rs = 0.f, rq = 0.f;
#pragma unroll
                for (int nt = 0; nt < 4; nt++) {
                    float2 v2 = make_float2(acc[mt][nt][half * 2], acc[mt][nt][half * 2 + 1]);
                    *(float2*)&Cp[o * NT + n0 + nb + nt * 8 + 2 * lqe] = v2;
                    if (MODE == 3) { rs += v2.x + v2.y; rq += v2.x * v2.x + v2.y * v2.y; }
                }
                if (MODE == 3) {
                    atomicAdd(&ssum[o - m0], rs);
                    atomicAdd(&ssq[o - m0], rq);
                }
            }
        }
    }

    if (MODE == 0 || MODE == 3) {
        __syncthreads();
        const int base = (MODE == 0) ? 0 : 1376;
        const int Csz  = (MODE == 0) ? 128 : 256;
        if (tid < 128) {
            atomicAdd(&g_st[base + m0 + tid], (double)ssum[tid]);
            atomicAdd(&g_st[base + Csz + m0 + tid], (double)ssq[tid]);
        }
    }
}

// ---------------------------------------------------------------------------
// prep_S: precompute sliding-window tables of the rel embedding.
// grid (12, 2): blockIdx.y selects direction (0=h, 1=w).
// ---------------------------------------------------------------------------
__global__ void __launch_bounds__(256) prep_S(const float* __restrict__ rel_h,
                                              const float* __restrict__ rel_w) {
    const int dir = blockIdx.y;
    const float* rel = dir ? rel_w : rel_h;
    __shared__ float r[16][127];
    for (int t = threadIdx.x; t < 16 * 127; t += 256) r[t / 127][t % 127] = rel[t];
    __syncthreads();
    const int g0 = blockIdx.x * 256 + threadIdx.x;
    const int gs = gridDim.x * 256;
    for (int t = g0; t < 1024; t += gs) {
        int which = t >> 9, i = (t >> 6) & 7, d = t & 63;
        const float* rr = r[which * 8 + i];
        float s = 0.f;
        for (int u = 0; u < 64; u++) s += rr[d + u];
        (which ? g_Tk[dir] : g_Tq[dir])[i * 64 + d] = s;
    }
    for (int t = g0; t < 4608; t += gs) {
        int which = t / 2304, rem = t % 2304, p = rem >> 6, d = rem & 63;
        const float* a = r[which * 8 + c_pi[p]];
        const float* b = r[which * 8 + c_pj[p]];
        float s = 0.f;
        for (int u = 0; u < 64; u++) s = fmaf(a[d + u], b[d + u], s);
        (which ? g_Sk[dir] : g_Sq[dir])[p * 64 + d] = s;
    }
}

// ---------------------------------------------------------------------------
// att_stats: BN statistics of qr/kr/dots without materializing logits.
// ---------------------------------------------------------------------------
__global__ void __launch_bounds__(256) att_stats(int stoff, int dir) {
    const int bw = blockIdx.x, tid = threadIdx.x;
    __shared__ float qT[8][512];   // [h][d*8 + i]
    __shared__ float kT[8][512];
    __shared__ float rsq[8][8], rsk[8][8], tqs[8][8], tks[8][8];

    for (int t = tid; t < 8192; t += 256) {
        int which = t >> 12, o = (t >> 6) & 63, d = t & 63;
        float v = g_qkv[(which * 64 + o) * NT + bw * 64 + d];
        int h = o & 7, i = o >> 3;
        if (which == 0) qT[h][d * 8 + i] = v; else kT[h][d * 8 + i] = v;
    }
    __syncthreads();

    const int h = tid >> 5, lane = tid & 31;
    const float* Tq = g_Tq[dir];
    const float* Tk = g_Tk[dir];
    const float* Sq = g_Sq[dir];
    const float* Sk = g_Sk[dir];
    if (lane < 8) {
        float s = 0.f;
        for (int d = 0; d < 64; d++) s += qT[h][d * 8 + lane];
        rsq[h][lane] = s;
    } else if (lane < 16) {
        int i = lane - 8; float s = 0.f;
        for (int d = 0; d < 64; d++) s += kT[h][d * 8 + i];
        rsk[h][i] = s;
    } else if (lane < 24) {
        int i = lane - 16; float s = 0.f;
        for (int d = 0; d < 64; d++) s = fmaf(qT[h][d * 8 + i], __ldg(&Tq[i * 64 + d]), s);
        tqs[h][i] = s;
    } else {
        int i = lane - 24; float s = 0.f;
        for (int d = 0; d < 64; d++) s = fmaf(kT[h][d * 8 + i], __ldg(&Tk[i * 64 + d]), s);
        tks[h][i] = s;
    }

    float dsq = 0.f, wq = 0.f, wk = 0.f;
    for (int p = lane; p < 36; p += 32) {
        int i = c_pi[p], i2 = c_pj[p];
        float m = (i == i2) ? 1.f : 2.f;
        float gq = 0.f, wqp = 0.f, gk = 0.f, wkp = 0.f;
        for (int d = 0; d < 64; d++) {
            float pq = qT[h][d * 8 + i] * qT[h][d * 8 + i2];
            gq += pq; wqp = fmaf(pq, __ldg(&Sq[p * 64 + d]), wqp);
            float pk = kT[h][d * 8 + i] * kT[h][d * 8 + i2];
            gk += pk; wkp = fmaf(pk, __ldg(&Sk[p * 64 + d]), wkp);
        }
        dsq = fmaf(m * gq, gk, dsq); wq = fmaf(m, wqp, wq); wk = fmaf(m, wkp, wk);
    }
#pragma unroll
    for (int off = 16; off; off >>= 1) {
        dsq += __shfl_xor_sync(~0u, dsq, off);
        wq  += __shfl_xor_sync(~0u, wq,  off);
        wk  += __shfl_xor_sync(~0u, wk,  off);
    }
    __syncwarp();
    if (lane == 0) {
        float ds = 0.f, qs = 0.f, ks = 0.f;
#pragma unroll
        for (int i = 0; i < 8; i++) {
            ds = fmaf(rsq[h][i], rsk[h][i], ds);
            qs += tqs[h][i]; ks += tks[h][i];
        }
        atomicAdd(&g_st[stoff + h * 3 + 0], (double)qs);
        atomicAdd(&g_st[stoff + h * 3 + 1], (double)ks);
        atomicAdd(&g_st[stoff + h * 3 + 2], (double)ds);
        atomicAdd(&g_st[stoff + 24 + h * 3 + 0], (double)wq);
        atomicAdd(&g_st[stoff + 24 + h * 3 + 1], (double)wk);
        atomicAdd(&g_st[stoff + 24 + h * 3 + 2], (double)dsq);
    }
}

// ---------------------------------------------------------------------------
// att_pass2: logits (BN applied) -> softmax -> sv & sve.  Conflict-free:
// Phase A: warp = 8 d-rows, lane = j (stride-1 rel reads, broadcast q/k).
// Phase B: warp = 2 i-channels, lane = d (stride-1 rel, pitch-65 sat).
// ---------------------------------------------------------------------------
__global__ void __launch_bounds__(256) att_pass2(const float* __restrict__ rel,
                                                 int sba, int sto) {
    const int bw = blockIdx.x, h = blockIdx.y, tid = threadIdx.x;
    const int warp = tid >> 5, lane = tid & 31;
    __shared__ float sq[8][65], sk[8][65], svv[16][65];
    __shared__ float srel[32][129];
    __shared__ float sat[64][65];

#pragma unroll
    for (int r = 0; r < 8; r++) {
        int t = tid + r * 256;
        int o = t >> 6, d = t & 63;
        float v = g_qkv[(o * 8 + h) * NT + bw * 64 + d];
        if (o < 8) sq[o][d] = v;
        else if (o < 16) sk[o - 8][d] = v;
        else svv[o - 16][d] = v;
    }
    for (int t = tid; t < 32 * 127; t += 256) srel[t / 127][t % 127] = rel[t];
    const float s0 = g_sb[sba + h * 3], s1v = g_sb[sba + h * 3 + 1], s2v = g_sb[sba + h * 3 + 2];
    const float bsum = g_sb[sba + 24 + h * 3] + g_sb[sba + 24 + h * 3 + 1]
                     + g_sb[sba + 24 + h * 3 + 2];
    __syncthreads();

    {   // ---- Phase A: logits + softmax.  j0 = lane, j1 = lane + 32. ----
        float kk0[8], kk1[8];
#pragma unroll
        for (int i = 0; i < 8; i++) {
            kk0[i] = sk[i][lane];
            kk1[i] = sk[i][lane + 32];
        }
        const int dbase = warp * 8;
#pragma unroll
        for (int r = 0; r < 8; r++) {
            const int d = dbase + r;
            const int m0 = d - lane + 63;
            float qr0 = 0, kr0 = 0, dt0 = 0, qr1 = 0, kr1 = 0, dt1 = 0;
#pragma unroll
            for (int i = 0; i < 8; i++) {
                float qi  = sq[i][d];
                float kdi = sk[i][d];
                float rq0 = srel[i][m0],     rq1 = srel[i][m0 - 32];
                float rk0 = srel[8 + i][m0], rk1 = srel[8 + i][m0 - 32];
                qr0 = fmaf(qi, rq0, qr0);   qr1 = fmaf(qi, rq1, qr1);
                kr0 = fmaf(kdi, rk0, kr0);  kr1 = fmaf(kdi, rk1, kr1);
                dt0 = fmaf(qi, kk0[i], dt0); dt1 = fmaf(qi, kk1[i], dt1);
            }
            float l0 = qr0 * s0 + kr0 * s1v + dt0 * s2v + bsum;
            float l1 = qr1 * s0 + kr1 * s1v + dt1 * s2v + bsum;
            float mx = fmaxf(l0, l1);
#pragma unroll
            for (int off = 16; off; off >>= 1)
                mx = fmaxf(mx, __shfl_xor_sync(~0u, mx, off));
            float e0 = __expf(l0 - mx), e1 = __expf(l1 - mx);
            float se = e0 + e1;
#pragma unroll
            for (int off = 16; off; off >>= 1)
                se += __shfl_xor_sync(~0u, se, off);
            float inv = 1.f / se;
            sat[d][lane]      = e0 * inv;
            sat[d][lane + 32] = e1 * inv;
        }
    }
    __syncthreads();

    {   // ---- Phase B: sv & sve.  i0 = 2*warp, i1 = i0+1; da = lane, db = lane+32.
        const int i0 = warp * 2, i1 = i0 + 1;
        const int da = lane, db = lane + 32;
        float av0a = 0, av0b = 0, av1a = 0, av1b = 0;
        float ae0a = 0, ae0b = 0, ae1a = 0, ae1b = 0;
        const float* r0 = &srel[16 + i0][0];
        const float* r1 = &srel[16 + i1][0];
#pragma unroll 4
        for (int j = 0; j < 64; j++) {
            float Aa = sat[da][j];
            float Ab = sat[db][j];
            float v0 = svv[i0][j], v1 = svv[i1][j];
            float r0a = r0[da - j + 63], r0b = r0[db - j + 63];
            float r1a = r1[da - j + 63], r1b = r1[db - j + 63];
            av0a = fmaf(Aa, v0, av0a);  av0b = fmaf(Ab, v0, av0b);
            av1a = fmaf(Aa, v1, av1a);  av1b = fmaf(Ab, v1, av1b);
            ae0a = fmaf(Aa, r0a, ae0a); ae0b = fmaf(Ab, r0b, ae0b);
            ae1a = fmaf(Aa, r1a, ae1a); ae1b = fmaf(Ab, r1b, ae1b);
        }
        const int ch0 = h * 16 + i0, ch1 = h * 16 + i1;
        g_outatt[ch0 * NT + bw * 64 + da] = ae0a;
        g_outatt[ch0 * NT + bw * 64 + db] = ae0b;
        g_outatt[ch1 * NT + bw * 64 + da] = ae1a;
        g_outatt[ch1 * NT + bw * 64 + db] = ae1b;
        g_outatt[(128 + ch0) * NT + bw * 64 + da] = av0a;
        g_outatt[(128 + ch0) * NT + bw * 64 + db] = av0b;
        g_outatt[(128 + ch1) * NT + bw * 64 + da] = av1a;
        g_outatt[(128 + ch1) * NT + bw * 64 + db] = av1b;

        float se0 = ae0a + ae0b, qe0 = ae0a * ae0a + ae0b * ae0b;
        float se1 = ae1a + ae1b, qe1 = ae1a * ae1a + ae1b * ae1b;
        float sv0 = av0a + av0b, qv0 = av0a * av0a + av0b * av0b;
        float sv1 = av1a + av1b, qv1 = av1a * av1a + av1b * av1b;
#pragma unroll
        for (int off = 16; off; off >>= 1) {
            se0 += __shfl_xor_sync(~0u, se0, off); qe0 += __shfl_xor_sync(~0u, qe0, off);
            se1 += __shfl_xor_sync(~0u, se1, off); qe1 += __shfl_xor_sync(~0u, qe1, off);
            sv0 += __shfl_xor_sync(~0u, sv0, off); qv0 += __shfl_xor_sync(~0u, qv0, off);
            sv1 += __shfl_xor_sync(~0u, sv1, off); qv1 += __shfl_xor_sync(~0u, qv1, off);
        }
        if (lane == 0) {
            atomicAdd(&g_st[sto + ch0], (double)se0);
            atomicAdd(&g_st[sto + ch1], (double)se1);
            atomicAdd(&g_st[sto + 256 + ch0], (double)qe0);
            atomicAdd(&g_st[sto + 256 + ch1], (double)qe1);
            atomicAdd(&g_st[sto + 128 + ch0], (double)sv0);
            atomicAdd(&g_st[sto + 128 + ch1], (double)sv1);
            atomicAdd(&g_st[sto + 256 + 128 + ch0], (double)qv0);
            atomicAdd(&g_st[sto + 256 + 128 + ch1], (double)qv1);
        }
    }
}

// combine att1: x3[c][b][h][w] = bn(sve) + bn(sv), with h<->w transpose
__global__ void __launch_bounds__(256) combine1() {
    const int c = blockIdx.x, b = blockIdx.y, tid = threadIdx.x;
    __shared__ float tile[64][65];
    const float sA = g_sb[304 + c],        bA = g_sb[304 + 256 + c];
    const float sB = g_sb[304 + c + 128],  bB = g_sb[304 + 256 + c + 128];
    const float* pA = g_outatt + c * NT + b * 4096;
    const float* pB = g_outatt + (c + 128) * NT + b * 4096;
    for (int t = tid; t < 4096; t += 256)
        tile[t >> 6][t & 63] = pA[t] * sA + bA + pB[t] * sB + bB;
    __syncthreads();
    float* q = g_x3 + c * NT + b * 4096;
    for (int t = tid; t < 4096; t += 256)
        q[t] = tile[t & 63][t >> 6];
}

// final: out = relu(bn(conv_out) + x_in)
__global__ void __launch_bounds__(256) final_k(const float* __restrict__ x_in,
                                               float* __restrict__ out) {
    int idx = blockIdx.x * 256 + threadIdx.x;
    int o = idx >> 15, m = idx & (NT - 1);
    int b = m >> 12, hw = m & 4095;
    float v = g_y2[idx] * g_sb[1376 + o] + g_sb[1376 + 256 + o];
    int oidx = (b * 256 + o) * 4096 + hw;
    v += x_in[oidx];
    out[oidx] = fmaxf(v, 0.f);
}

// ---------------------------------------------------------------------------
extern "C" void kernel_launch(void* const* d_in, const int* in_sizes, int n_in,
                              void* d_out, int out_size) {
    (void)in_sizes; (void)n_in; (void)out_size;
    const float* x_in   = (const float*)d_in[0];
    const float* w_in   = (const float*)d_in[1];
    const float* g_in   = (const float*)d_in[2];
    const float* b_in   = (const float*)d_in[3];
    const float* w_out  = (const float*)d_in[4];
    const float* g_out  = (const float*)d_in[5];
    const float* b_out  = (const float*)d_in[6];
    const float* wqkv_h = (const float*)d_in[7];
    const float* rel_h  = (const float*)d_in[8];
    const float* ga_h   = (const float*)d_in[9];
    const float* ba_h   = (const float*)d_in[10];
    const float* go_h   = (const float*)d_in[11];
    const float* bo_h   = (const float*)d_in[12];
    const float* wqkv_w = (const float*)d_in[13];
    const float* rel_w  = (const float*)d_in[14];
    const float* ga_w   = (const float*)d_in[15];
    const float* ba_w   = (const float*)d_in[16];
    const float* go_w   = (const float*)d_in[17];
    const float* bo_w   = (const float*)d_in[18];

    cudaFuncSetAttribute(gemm_k<0>, cudaFuncAttributeMaxDynamicSharedMemorySize, GEMM_SMEM_BYTES);
    cudaFuncSetAttribute(gemm_k<1>, cudaFuncAttributeMaxDynamicSharedMemorySize, GEMM_SMEM_BYTES);
    cudaFuncSetAttribute(gemm_k<2>, cudaFuncAttributeMaxDynamicSharedMemorySize, GEMM_SMEM_BYTES);
    cudaFuncSetAttribute(gemm_k<3>, cudaFuncAttributeMaxDynamicSharedMemorySize, GEMM_SMEM_BYTES);

    zero_stats<<<8, 256>>>();                                   // 0
    prep_S<<<dim3(12, 2), 256>>>(rel_h, rel_w);                 // 1
    prep_A4<<<512, 256>>>(w_in, wqkv_h, wqkv_w, w_out);         // 2

    // conv-in (+stats) -> y1                                   // 3 (profiled)
    gemm_k<0><<<dim3(256, 1), 256, GEMM_SMEM_BYTES>>>(x_in, 256);
    make_scale<<<2, 64>>>(0, g_in, b_in, 0, 128, 1.f / 32768.f);

    // --- axial attention along H ---
    gemm_k<1><<<dim3(256, 2), 256, GEMM_SMEM_BYTES>>>(nullptr, 128);
    att_stats<<<512, 256>>>(256, 0);
    make_scale<<<1, 64>>>(256, ga_h, ba_h, 256, 24, 1.f / 2097152.f);
    att_pass2<<<dim3(512, 8), 256>>>(rel_h, 256, 304);
    make_scale<<<4, 64>>>(304, go_h, bo_h, 304, 256, 1.f / 32768.f);
    combine1<<<dim3(128, 8), 256>>>();

    // --- axial attention along W ---
    gemm_k<2><<<dim3(256, 2), 256, GEMM_SMEM_BYTES>>>(nullptr, 128);
    att_stats<<<512, 256>>>(816, 1);
    make_scale<<<1, 64>>>(816, ga_w, ba_w, 816, 24, 1.f / 2097152.f);
    att_pass2<<<dim3(512, 8), 256>>>(rel_w, 816, 864);
    make_scale<<<4, 64>>>(864, go_w, bo_w, 864, 256, 1.f / 32768.f);

    // conv-out (fused combine2 at load, +stats) -> y2
    gemm_k<3><<<dim3(256, 2), 256, GEMM_SMEM_BYTES>>>(nullptr, 128);
    make_scale<<<4, 64>>>(1376, g_out, b_out, 1376, 256, 1.f / 32768.f);

    final_k<<<32768, 256>>>(x_in, (float*)d_out);
}

// round 12
// speedup vs baseline: 1.1291x; 1.1096x over previous
#include <cuda_runtime.h>
#include <cuda_bf16.h>
#include <cstdint>

// ---------------------------------------------------------------------------
// Problem constants
//   B=8, C_IN=256, DIM=64, HEADS=8, D_IN=128, DKQ=8, DV=16, QKV=32
//   N = B*DIM*DIM = 32768 "pixels"; sequences: 512 of length 64
// ---------------------------------------------------------------------------
#define NT 32768
#define EPSV 1e-5f

__device__ float  g_y1[128 * NT];      // conv-in raw output, layout [c][b][w][h]
__device__ float  g_qkv[256 * NT];     // qkv, layout [o][bw][pos]
__device__ float  g_outatt[256 * NT];  // attention out (sve ch 0..127, sv 128..255)
__device__ float  g_x3[128 * NT];      // att1 combined (input to qkv2 GEMM)
__device__ float  g_y2[256 * NT];      // conv-out raw output [o][n1]
// stats offsets: convin @0(256) att1 @256(48) out1 @304(512) att2 @816(48)
//                out2 @864(512) convout @1376(512)
__device__ double g_st[1888];
__device__ float  g_sb[1888];

// Pre-converted weights: packed bf16x2 fragment-major hi/lo (m16n8k16 A frags)
//   mat0 w_in (128x256) @0, mat1 wqkv_h @16384, mat2 wqkv_w @32768,
//   mat3 w_out @49152   (each 16384 u32)
__device__ uint32_t g_Ah[65536], g_Al[65536];

// Precomputed rel-embedding tables, double-buffered per direction
__device__ float g_Tq[2][8 * 64], g_Tk[2][8 * 64];
__device__ float g_Sq[2][36 * 64], g_Sk[2][36 * 64];

__device__ const int c_pi[36] = {0,0,0,0,0,0,0,0, 1,1,1,1,1,1,1, 2,2,2,2,2,2,
                                 3,3,3,3,3, 4,4,4,4, 5,5,5, 6,6, 7};
__device__ const int c_pj[36] = {0,1,2,3,4,5,6,7, 1,2,3,4,5,6,7, 2,3,4,5,6,7,
                                 3,4,5,6,7, 4,5,6,7, 5,6,7, 6,7, 7};

__global__ void zero_stats() {
    int i = blockIdx.x * 256 + threadIdx.x;
    if (i < 1888) g_st[i] = 0.0;
}

__global__ void make_scale(int stoff, const float* __restrict__ gamma,
                           const float* __restrict__ beta, int sboff, int C, float invN) {
    int t = blockIdx.x * 64 + threadIdx.x;
    if (t >= C) return;
    double mean = g_st[stoff + t] * (double)invN;
    double var  = g_st[stoff + C + t] * (double)invN - mean * mean;
    float s = gamma[t] * rsqrtf((float)var + EPSV);
    g_sb[sboff + t]     = s;
    g_sb[sboff + C + t] = beta[t] - (float)mean * s;
}

// ---------------------------------------------------------------------------
// 3xBF16 helpers: x = bh + bl, products bh*bh + bl*bh + bh*bl (drop bl*bl)
// ---------------------------------------------------------------------------
__device__ __forceinline__ uint32_t pack_bf16x2(float lo_elem, float hi_elem) {
    uint32_t p;
    asm("cvt.rn.bf16x2.f32 %0, %1, %2;" : "=r"(p) : "f"(hi_elem), "f"(lo_elem));
    return p;
}
// pack hi parts of (x0,x1) and return residuals
__device__ __forceinline__ uint32_t split_pack(float x0, float x1, float& r0, float& r1) {
    uint32_t p = pack_bf16x2(x0, x1);
    __nv_bfloat162 b = *reinterpret_cast<__nv_bfloat162*>(&p);
    r0 = x0 - __bfloat162float(b.x);
    r1 = x1 - __bfloat162float(b.y);
    return p;
}

#define MMA_BF16(c, a0, a1, a2, a3, b0, b1)                                    \
    asm volatile(                                                              \
        "mma.sync.aligned.m16n8k16.row.col.f32.bf16.bf16.f32 "                 \
        "{%0,%1,%2,%3}, {%4,%5,%6,%7}, {%8,%9}, {%0,%1,%2,%3};"                \
        : "+f"(c[0]), "+f"(c[1]), "+f"(c[2]), "+f"(c[3])                       \
        : "r"(a0), "r"(a1), "r"(a2), "r"(a3), "r"(b0), "r"(b1))

#define CP_ASYNC16(dst_u32, src_ptr)                                           \
    asm volatile("cp.async.cg.shared.global [%0], [%1], 16;"                   \
                 :: "r"(dst_u32), "l"(src_ptr))
#define CP_COMMIT()  asm volatile("cp.async.commit_group;")
#define CP_WAIT0()   asm volatile("cp.async.wait_group 0;" ::: "memory")

// ---------------------------------------------------------------------------
// prep_A4: convert the 4 weight matrices to packed bf16x2 fragment-major hi/lo.
// m16n8k16 A frag (16m x 16k): within-frag element (m',k): kp=k>>1,
//   lane = (m'&7)*4 + (kp&3), reg = ((kp>>2)&1)*2 + (m'>>3), half = k&1.
//   word = frag*128 + lane*4 + reg;  frag = (k>>4)*(M>>4) + (m>>4)
// One thread per k-pair (65536 pairs).
// ---------------------------------------------------------------------------
__global__ void __launch_bounds__(256) prep_A4(const float* __restrict__ w_in,
                                               const float* __restrict__ wqkv_h,
                                               const float* __restrict__ wqkv_w,
                                               const float* __restrict__ w_out) {
    int idx = blockIdx.x * 256 + threadIdx.x;   // 0..65535
    int mat = idx >> 14;
    int e2 = idx & 16383;
    const float* src = (mat == 0) ? w_in : (mat == 1) ? wqkv_h
                      : (mat == 2) ? wqkv_w : w_out;
    int M, K, m, kp;
    if (mat == 0) { M = 128; K = 256; m = e2 >> 7; kp = e2 & 127; }
    else          { M = 256; K = 128; m = e2 >> 6; kp = e2 & 63; }
    float x0 = src[m * K + kp * 2];
    float x1 = src[m * K + kp * 2 + 1];
    float r0, r1;
    uint32_t hi = split_pack(x0, x1, r0, r1);
    uint32_t lo = pack_bf16x2(r0, r1);
    int mp = m & 15, kpp = kp & 7;
    int frag = (kp >> 3) * (M >> 4) + (m >> 4);
    int lane = (mp & 7) * 4 + (kpp & 3);
    int reg  = ((kpp >> 2) & 1) * 2 + (mp >> 3);
    int word = (mat << 14) + frag * 128 + lane * 4 + reg;
    g_Ah[word] = hi;
    g_Al[word] = lo;
}

// ---------------------------------------------------------------------------
// Pipelined GEMM via 3xBF16 mma.sync m16n8k16, double-buffered static smem.
//   A: one contiguous 4KB cp.async block per stage (pre-packed fragments).
//   B: prefetch to regs at top of iter; split+pack+STS into next stage after
//      compute.  B frag words (hi/lo interleaved): frag*132 + lane*4 +
//      {b0h,b0l,b1h,b1l}; compute: one LDS.128 per fragment.
// MODE 0 conv-in (gather x_in, scatter y1 + stats), 1 qkv (BN+relu at load),
// 2 qkv plain (reads x3), 3 conv-out (fused combine2 at load, +stats).
// Block tile 128x128, k-chunk 16; 8 warps (64m x 32n); 2 CTA/SM.
// ---------------------------------------------------------------------------
template <int MODE>
__device__ __forceinline__ float4 gemm_loadB(const float* __restrict__ Bext,
                                             int n0, int k, int nn) {
    if (MODE == 0) {
        return *(const float4*)&Bext[(n0 >> 12) * 1048576 + k * 4096 + (n0 & 4095) + nn];
    } else if (MODE == 3) {
        float4 a = *(const float4*)&g_outatt[k * NT + n0 + nn];
        float4 b = *(const float4*)&g_outatt[(128 + k) * NT + n0 + nn];
        float sA = g_sb[864 + k],       bA = g_sb[864 + 256 + k];
        float sB = g_sb[864 + 128 + k], bB = g_sb[864 + 256 + 128 + k];
        float4 v;
        v.x = fmaxf(a.x * sA + bA + b.x * sB + bB, 0.f);
        v.y = fmaxf(a.y * sA + bA + b.y * sB + bB, 0.f);
        v.z = fmaxf(a.z * sA + bA + b.z * sB + bB, 0.f);
        v.w = fmaxf(a.w * sA + bA + b.w * sB + bB, 0.f);
        return v;
    } else {
        const float* Bp = (MODE == 1) ? g_y1 : g_x3;
        float4 v = *(const float4*)&Bp[k * NT + n0 + nn];
        if (MODE == 1) {
            float s = g_sb[k], bi = g_sb[128 + k];
            v.x = fmaxf(fmaf(v.x, s, bi), 0.f);
            v.y = fmaxf(fmaf(v.y, s, bi), 0.f);
            v.z = fmaxf(fmaf(v.z, s, bi), 0.f);
            v.w = fmaxf(fmaf(v.w, s, bi), 0.f);
        }
        return v;
    }
}

template <int MODE>
__global__ void __launch_bounds__(256, 2) gemm_k(const float* __restrict__ Bext, int K) {
    constexpr int M     = (MODE == 0) ? 128 : 256;
    constexpr int WOFF4 = (MODE == 0) ? 0 : ((MODE == 1) ? 16384
                         : ((MODE == 2) ? 32768 : 49152));
    constexpr int KFR   = M >> 4;              // m-frags per k-group
    __shared__ uint32_t Ah[2][1024], Al[2][1024];
    __shared__ uint32_t Bs[2][2112];           // 16 frags * 132
    __shared__ float ssum[128], ssq[128];
    const int n0 = blockIdx.x * 128;
    const int m0 = blockIdx.y * 128;
    const int tid = threadIdx.x;
    const int warp = tid >> 5, lane = tid & 31;
    const int mb4 = (warp & 1) * 4;            // A frag base within chunk
    const int nb4 = (warp >> 1) * 4;           // B frag base within chunk
    const int bn4 = lane * 4;                  // 4 consecutive n per thread

    float* Cp = (MODE == 0) ? g_y1 : ((MODE == 3) ? g_y2 : g_qkv);

    float acc[4][4][4];
#pragma unroll
    for (int mt = 0; mt < 4; mt++)
#pragma unroll
        for (int nt = 0; nt < 4; nt++)
#pragma unroll
            for (int c = 0; c < 4; c++) acc[mt][nt][c] = 0.f;

    float4 v0, v1;   // B rows k=2*warp, 2*warp+1

    // B staging store: for n = bn4+j, kp = warp:
    //   word = (n>>3)*132 + ((n&7)*4 + (warp&3))*4 + (warp>>2)*2  (+1 for lo)
    auto stageB = [&](int stg) {
        const float* e0 = (const float*)&v0;
        const float* e1 = (const float*)&v1;
#pragma unroll
        for (int j = 0; j < 4; j++) {
            float r0, r1;
            uint32_t hi = split_pack(e0[j], e1[j], r0, r1);
            uint32_t lo = pack_bf16x2(r0, r1);
            int n = bn4 + j;
            int word = (n >> 3) * 132 + ((n & 7) * 4 + (warp & 3)) * 4 + (warp >> 2) * 2;
            *(uint2*)&Bs[stg][word] = make_uint2(hi, lo);
        }
    };
    auto loadA = [&](int stg, int c) {
        int gw = WOFF4 + (c * KFR + (m0 >> 4)) * 128 + tid * 4;
        uint32_t dh = (uint32_t)__cvta_generic_to_shared(&Ah[stg][tid * 4]);
        uint32_t dl = (uint32_t)__cvta_generic_to_shared(&Al[stg][tid * 4]);
        CP_ASYNC16(dh, &g_Ah[gw]);
        CP_ASYNC16(dl, &g_Al[gw]);
    };

    // --- prologue: chunk 0 into stage 0 ---
    v0 = gemm_loadB<MODE>(Bext, n0, 2 * warp, bn4);
    v1 = gemm_loadB<MODE>(Bext, n0, 2 * warp + 1, bn4);
    loadA(0, 0);
    CP_COMMIT();
    stageB(0);
    CP_WAIT0();
    __syncthreads();

    const int nchunk = K >> 4;
    for (int c0 = 0; c0 < nchunk; c0++) {
        const int cur = c0 & 1, nxt = cur ^ 1;
        const bool more = (c0 + 1 < nchunk);

        if (more) {
            const int k0n = (c0 + 1) * 16;
            v0 = gemm_loadB<MODE>(Bext, n0, k0n + 2 * warp, bn4);
            v1 = gemm_loadB<MODE>(Bext, n0, k0n + 2 * warp + 1, bn4);
            loadA(nxt, c0 + 1);
            CP_COMMIT();
        }

        // ---- compute from stage cur: 48 MMAs per warp ----
        uint4 bq[4];
#pragma unroll
        for (int nt = 0; nt < 4; nt++)
            bq[nt] = *(const uint4*)&Bs[cur][(nb4 + nt) * 132 + lane * 4];
#pragma unroll
        for (int mt = 0; mt < 4; mt++) {
            uint4 ah = *(const uint4*)&Ah[cur][(mb4 + mt) * 128 + lane * 4];
            uint4 al = *(const uint4*)&Al[cur][(mb4 + mt) * 128 + lane * 4];
#pragma unroll
            for (int nt = 0; nt < 4; nt++) {
                MMA_BF16(acc[mt][nt], ah.x, ah.y, ah.z, ah.w, bq[nt].x, bq[nt].z);
                MMA_BF16(acc[mt][nt], al.x, al.y, al.z, al.w, bq[nt].x, bq[nt].z);
                MMA_BF16(acc[mt][nt], ah.x, ah.y, ah.z, ah.w, bq[nt].y, bq[nt].w);
            }
        }

        if (more) {
            stageB(nxt);
            CP_WAIT0();
            __syncthreads();
        }
    }
    __syncthreads();

    if (MODE == 0 || MODE == 3) {
        for (int t = tid; t < 128; t += 256) { ssum[t] = 0.f; ssq[t] = 0.f; }
        __syncthreads();
    }

    const int mb = (warp & 1) * 64, nb = (warp >> 1) * 32;
    const int lqe = lane & 3, lre = lane >> 2;
    if (MODE == 0) {
        const int bb = n0 >> 12, hw0 = n0 & 4095;
#pragma unroll
        for (int mt = 0; mt < 4; mt++) {
#pragma unroll
            for (int half = 0; half < 2; half++) {
                int o = mb + mt * 16 + lre + half * 8;  // m0 == 0
                float rs = 0.f, rq = 0.f;
#pragma unroll
                for (int nt = 0; nt < 4; nt++) {
#pragma unroll
                    for (int cc = 0; cc < 2; cc++) {
                        int hw = hw0 + nb + nt * 8 + 2 * lqe + cc;
                        float v = acc[mt][nt][half * 2 + cc];
                        Cp[o * NT + bb * 4096 + (hw & 63) * 64 + (hw >> 6)] = v;
                        rs += v; rq += v * v;
                    }
                }
                atomicAdd(&ssum[o], rs);
                atomicAdd(&ssq[o], rq);
            }
        }
    } else {
#pragma unroll
        for (int mt = 0; mt < 4; mt++) {
#pragma unroll
            for (int half = 0; half < 2; half++) {
                int o = m0 + mb + mt * 16 + lre + half * 8;
                float rs = 0.f, rq = 0.f;
#pragma unroll
                for (int nt = 0; nt < 4; nt++) {
                    float2 v2 = make_float2(acc[mt][nt][half * 2], acc[mt][nt][half * 2 + 1]);
                    *(float2*)&Cp[o * NT + n0 + nb + nt * 8 + 2 * lqe] = v2;
                    if (MODE == 3) { rs += v2.x + v2.y; rq += v2.x * v2.x + v2.y * v2.y; }
                }
                if (MODE == 3) {
                    atomicAdd(&ssum[o - m0], rs);
                    atomicAdd(&ssq[o - m0], rq);
                }
            }
        }
    }

    if (MODE == 0 || MODE == 3) {
        __syncthreads();
        const int base = (MODE == 0) ? 0 : 1376;
        const int Csz  = (MODE == 0) ? 128 : 256;
        if (tid < 128) {
            atomicAdd(&g_st[base + m0 + tid], (double)ssum[tid]);
            atomicAdd(&g_st[base + Csz + m0 + tid], (double)ssq[tid]);
        }
    }
}

// ---------------------------------------------------------------------------
// prep_S: precompute sliding-window tables of the rel embedding.
// grid (12, 2): blockIdx.y selects direction (0=h, 1=w).
// ---------------------------------------------------------------------------
__global__ void __launch_bounds__(256) prep_S(const float* __restrict__ rel_h,
                                              const float* __restrict__ rel_w) {
    const int dir = blockIdx.y;
    const float* rel = dir ? rel_w : rel_h;
    __shared__ float r[16][127];
    for (int t = threadIdx.x; t < 16 * 127; t += 256) r[t / 127][t % 127] = rel[t];
    __syncthreads();
    const int g0 = blockIdx.x * 256 + threadIdx.x;
    const int gs = gridDim.x * 256;
    for (int t = g0; t < 1024; t += gs) {
        int which = t >> 9, i = (t >> 6) & 7, d = t & 63;
        const float* rr = r[which * 8 + i];
        float s = 0.f;
        for (int u = 0; u < 64; u++) s += rr[d + u];
        (which ? g_Tk[dir] : g_Tq[dir])[i * 64 + d] = s;
    }
    for (int t = g0; t < 4608; t += gs) {
        int which = t / 2304, rem = t % 2304, p = rem >> 6, d = rem & 63;
        const float* a = r[which * 8 + c_pi[p]];
        const float* b = r[which * 8 + c_pj[p]];
        float s = 0.f;
        for (int u = 0; u < 64; u++) s = fmaf(a[d + u], b[d + u], s);
        (which ? g_Sk[dir] : g_Sq[dir])[p * 64 + d] = s;
    }
}

// ---------------------------------------------------------------------------
// att_stats: BN statistics of qr/kr/dots without materializing logits.
// ---------------------------------------------------------------------------
__global__ void __launch_bounds__(256) att_stats(int stoff, int dir) {
    const int bw = blockIdx.x, tid = threadIdx.x;
    __shared__ float qT[8][512];   // [h][d*8 + i]
    __shared__ float kT[8][512];
    __shared__ float rsq[8][8], rsk[8][8], tqs[8][8], tks[8][8];

    for (int t = tid; t < 8192; t += 256) {
        int which = t >> 12, o = (t >> 6) & 63, d = t & 63;
        float v = g_qkv[(which * 64 + o) * NT + bw * 64 + d];
        int h = o & 7, i = o >> 3;
        if (which == 0) qT[h][d * 8 + i] = v; else kT[h][d * 8 + i] = v;
    }
    __syncthreads();

    const int h = tid >> 5, lane = tid & 31;
    const float* Tq = g_Tq[dir];
    const float* Tk = g_Tk[dir];
    const float* Sq = g_Sq[dir];
    const float* Sk = g_Sk[dir];
    if (lane < 8) {
        float s = 0.f;
        for (int d = 0; d < 64; d++) s += qT[h][d * 8 + lane];
        rsq[h][lane] = s;
    } else if (lane < 16) {
        int i = lane - 8; float s = 0.f;
        for (int d = 0; d < 64; d++) s += kT[h][d * 8 + i];
        rsk[h][i] = s;
    } else if (lane < 24) {
        int i = lane - 16; float s = 0.f;
        for (int d = 0; d < 64; d++) s = fmaf(qT[h][d * 8 + i], __ldg(&Tq[i * 64 + d]), s);
        tqs[h][i] = s;
    } else {
        int i = lane - 24; float s = 0.f;
        for (int d = 0; d < 64; d++) s = fmaf(kT[h][d * 8 + i], __ldg(&Tk[i * 64 + d]), s);
        tks[h][i] = s;
    }

    float dsq = 0.f, wq = 0.f, wk = 0.f;
    for (int p = lane; p < 36; p += 32) {
        int i = c_pi[p], i2 = c_pj[p];
        float m = (i == i2) ? 1.f : 2.f;
        float gq = 0.f, wqp = 0.f, gk = 0.f, wkp = 0.f;
        for (int d = 0; d < 64; d++) {
            float pq = qT[h][d * 8 + i] * qT[h][d * 8 + i2];
            gq += pq; wqp = fmaf(pq, __ldg(&Sq[p * 64 + d]), wqp);
            float pk = kT[h][d * 8 + i] * kT[h][d * 8 + i2];
            gk += pk; wkp = fmaf(pk, __ldg(&Sk[p * 64 + d]), wkp);
        }
        dsq = fmaf(m * gq, gk, dsq); wq = fmaf(m, wqp, wq); wk = fmaf(m, wkp, wk);
    }
#pragma unroll
    for (int off = 16; off; off >>= 1) {
        dsq += __shfl_xor_sync(~0u, dsq, off);
        wq  += __shfl_xor_sync(~0u, wq,  off);
        wk  += __shfl_xor_sync(~0u, wk,  off);
    }
    __syncwarp();
    if (lane == 0) {
        float ds = 0.f, qs = 0.f, ks = 0.f;
#pragma unroll
        for (int i = 0; i < 8; i++) {
            ds = fmaf(rsq[h][i], rsk[h][i], ds);
            qs += tqs[h][i]; ks += tks[h][i];
        }
        atomicAdd(&g_st[stoff + h * 3 + 0], (double)qs);
        atomicAdd(&g_st[stoff + h * 3 + 1], (double)ks);
        atomicAdd(&g_st[stoff + h * 3 + 2], (double)ds);
        atomicAdd(&g_st[stoff + 24 + h * 3 + 0], (double)wq);
        atomicAdd(&g_st[stoff + 24 + h * 3 + 1], (double)wk);
        atomicAdd(&g_st[stoff + 24 + h * 3 + 2], (double)dsq);
    }
}

// ---------------------------------------------------------------------------
// att_pass2: logits (BN applied) -> softmax -> sv & sve.  Conflict-free.
// ---------------------------------------------------------------------------
__global__ void __launch_bounds__(256) att_pass2(const float* __restrict__ rel,
                                                 int sba, int sto) {
    const int bw = blockIdx.x, h = blockIdx.y, tid = threadIdx.x;
    const int warp = tid >> 5, lane = tid & 31;
    __shared__ float sq[8][65], sk[8][65], svv[16][65];
    __shared__ float srel[32][129];
    __shared__ float sat[64][65];

#pragma unroll
    for (int r = 0; r < 8; r++) {
        int t = tid + r * 256;
        int o = t >> 6, d = t & 63;
        float v = g_qkv[(o * 8 + h) * NT + bw * 64 + d];
        if (o < 8) sq[o][d] = v;
        else if (o < 16) sk[o - 8][d] = v;
        else svv[o - 16][d] = v;
    }
    for (int t = tid; t < 32 * 127; t += 256) srel[t / 127][t % 127] = rel[t];
    const float s0 = g_sb[sba + h * 3], s1v = g_sb[sba + h * 3 + 1], s2v = g_sb[sba + h * 3 + 2];
    const float bsum = g_sb[sba + 24 + h * 3] + g_sb[sba + 24 + h * 3 + 1]
                     + g_sb[sba + 24 + h * 3 + 2];
    __syncthreads();

    {   // ---- Phase A: logits + softmax ----
        float kk0[8], kk1[8];
#pragma unroll
        for (int i = 0; i < 8; i++) {
            kk0[i] = sk[i][lane];
            kk1[i] = sk[i][lane + 32];
        }
        const int dbase = warp * 8;
#pragma unroll
        for (int r = 0; r < 8; r++) {
            const int d = dbase + r;
            const int m0 = d - lane + 63;
            float qr0 = 0, kr0 = 0, dt0 = 0, qr1 = 0, kr1 = 0, dt1 = 0;
#pragma unroll
            for (int i = 0; i < 8; i++) {
                float qi  = sq[i][d];
                float kdi = sk[i][d];
                float rq0 = srel[i][m0],     rq1 = srel[i][m0 - 32];
                float rk0 = srel[8 + i][m0], rk1 = srel[8 + i][m0 - 32];
                qr0 = fmaf(qi, rq0, qr0);   qr1 = fmaf(qi, rq1, qr1);
                kr0 = fmaf(kdi, rk0, kr0);  kr1 = fmaf(kdi, rk1, kr1);
                dt0 = fmaf(qi, kk0[i], dt0); dt1 = fmaf(qi, kk1[i], dt1);
            }
            float l0 = qr0 * s0 + kr0 * s1v + dt0 * s2v + bsum;
            float l1 = qr1 * s0 + kr1 * s1v + dt1 * s2v + bsum;
            float mx = fmaxf(l0, l1);
#pragma unroll
            for (int off = 16; off; off >>= 1)
                mx = fmaxf(mx, __shfl_xor_sync(~0u, mx, off));
            float e0 = __expf(l0 - mx), e1 = __expf(l1 - mx);
            float se = e0 + e1;
#pragma unroll
            for (int off = 16; off; off >>= 1)
                se += __shfl_xor_sync(~0u, se, off);
            float inv = 1.f / se;
            sat[d][lane]      = e0 * inv;
            sat[d][lane + 32] = e1 * inv;
        }
    }
    __syncthreads();

    {   // ---- Phase B: sv & sve ----
        const int i0 = warp * 2, i1 = i0 + 1;
        const int da = lane, db = lane + 32;
        float av0a = 0, av0b = 0, av1a = 0, av1b = 0;
        float ae0a = 0, ae0b = 0, ae1a = 0, ae1b = 0;
        const float* r0 = &srel[16 + i0][0];
        const float* r1 = &srel[16 + i1][0];
#pragma unroll 4
        for (int j = 0; j < 64; j++) {
            float Aa = sat[da][j];
            float Ab = sat[db][j];
            float v0 = svv[i0][j], v1 = svv[i1][j];
            float r0a = r0[da - j + 63], r0b = r0[db - j + 63];
            float r1a = r1[da - j + 63], r1b = r1[db - j + 63];
            av0a = fmaf(Aa, v0, av0a);  av0b = fmaf(Ab, v0, av0b);
            av1a = fmaf(Aa, v1, av1a);  av1b = fmaf(Ab, v1, av1b);
            ae0a = fmaf(Aa, r0a, ae0a); ae0b = fmaf(Ab, r0b, ae0b);
            ae1a = fmaf(Aa, r1a, ae1a); ae1b = fmaf(Ab, r1b, ae1b);
        }
        const int ch0 = h * 16 + i0, ch1 = h * 16 + i1;
        g_outatt[ch0 * NT + bw * 64 + da] = ae0a;
        g_outatt[ch0 * NT + bw * 64 + db] = ae0b;
        g_outatt[ch1 * NT + bw * 64 + da] = ae1a;
        g_outatt[ch1 * NT + bw * 64 + db] = ae1b;
        g_outatt[(128 + ch0) * NT + bw * 64 + da] = av0a;
        g_outatt[(128 + ch0) * NT + bw * 64 + db] = av0b;
        g_outatt[(128 + ch1) * NT + bw * 64 + da] = av1a;
        g_outatt[(128 + ch1) * NT + bw * 64 + db] = av1b;

        float se0 = ae0a + ae0b, qe0 = ae0a * ae0a + ae0b * ae0b;
        float se1 = ae1a + ae1b, qe1 = ae1a * ae1a + ae1b * ae1b;
        float sv0 = av0a + av0b, qv0 = av0a * av0a + av0b * av0b;
        float sv1 = av1a + av1b, qv1 = av1a * av1a + av1b * av1b;
#pragma unroll
        for (int off = 16; off; off >>= 1) {
            se0 += __shfl_xor_sync(~0u, se0, off); qe0 += __shfl_xor_sync(~0u, qe0, off);
            se1 += __shfl_xor_sync(~0u, se1, off); qe1 += __shfl_xor_sync(~0u, qe1, off);
            sv0 += __shfl_xor_sync(~0u, sv0, off); qv0 += __shfl_xor_sync(~0u, qv0, off);
            sv1 += __shfl_xor_sync(~0u, sv1, off); qv1 += __shfl_xor_sync(~0u, qv1, off);
        }
        if (lane == 0) {
            atomicAdd(&g_st[sto + ch0], (double)se0);
            atomicAdd(&g_st[sto + ch1], (double)se1);
            atomicAdd(&g_st[sto + 256 + ch0], (double)qe0);
            atomicAdd(&g_st[sto + 256 + ch1], (double)qe1);
            atomicAdd(&g_st[sto + 128 + ch0], (double)sv0);
            atomicAdd(&g_st[sto + 128 + ch1], (double)sv1);
            atomicAdd(&g_st[sto + 256 + 128 + ch0], (double)qv0);
            atomicAdd(&g_st[sto + 256 + 128 + ch1], (double)qv1);
        }
    }
}

// combine att1: x3[c][b][h][w] = bn(sve) + bn(sv), with h<->w transpose
__global__ void __launch_bounds__(256) combine1() {
    const int c = blockIdx.x, b = blockIdx.y, tid = threadIdx.x;
    __shared__ float tile[64][65];
    const float sA = g_sb[304 + c],        bA = g_sb[304 + 256 + c];
    const float sB = g_sb[304 + c + 128],  bB = g_sb[304 + 256 + c + 128];
    const float* pA = g_outatt + c * NT + b * 4096;
    const float* pB = g_outatt + (c + 128) * NT + b * 4096;
    for (int t = tid; t < 4096; t += 256)
        tile[t >> 6][t & 63] = pA[t] * sA + bA + pB[t] * sB + bB;
    __syncthreads();
    float* q = g_x3 + c * NT + b * 4096;
    for (int t = tid; t < 4096; t += 256)
        q[t] = tile[t & 63][t >> 6];
}

// final: out = relu(bn(conv_out) + x_in)
__global__ void __launch_bounds__(256) final_k(const float* __restrict__ x_in,
                                               float* __restrict__ out) {
    int idx = blockIdx.x * 256 + threadIdx.x;
    int o = idx >> 15, m = idx & (NT - 1);
    int b = m >> 12, hw = m & 4095;
    float v = g_y2[idx] * g_sb[1376 + o] + g_sb[1376 + 256 + o];
    int oidx = (b * 256 + o) * 4096 + hw;
    v += x_in[oidx];
    out[oidx] = fmaxf(v, 0.f);
}

// ---------------------------------------------------------------------------
extern "C" void kernel_launch(void* const* d_in, const int* in_sizes, int n_in,
                              void* d_out, int out_size) {
    (void)in_sizes; (void)n_in; (void)out_size;
    const float* x_in   = (const float*)d_in[0];
    const float* w_in   = (const float*)d_in[1];
    const float* g_in   = (const float*)d_in[2];
    const float* b_in   = (const float*)d_in[3];
    const float* w_out  = (const float*)d_in[4];
    const float* g_out  = (const float*)d_in[5];
    const float* b_out  = (const float*)d_in[6];
    const float* wqkv_h = (const float*)d_in[7];
    const float* rel_h  = (const float*)d_in[8];
    const float* ga_h   = (const float*)d_in[9];
    const float* ba_h   = (const float*)d_in[10];
    const float* go_h   = (const float*)d_in[11];
    const float* bo_h   = (const float*)d_in[12];
    const float* wqkv_w = (const float*)d_in[13];
    const float* rel_w  = (const float*)d_in[14];
    const float* ga_w   = (const float*)d_in[15];
    const float* ba_w   = (const float*)d_in[16];
    const float* go_w   = (const float*)d_in[17];
    const float* bo_w   = (const float*)d_in[18];

    zero_stats<<<8, 256>>>();                                   // 0
    prep_S<<<dim3(12, 2), 256>>>(rel_h, rel_w);                 // 1
    prep_A4<<<256, 256>>>(w_in, wqkv_h, wqkv_w, w_out);         // 2

    // conv-in (+stats) -> y1                                   // 3 (profiled)
    gemm_k<0><<<dim3(256, 1), 256>>>(x_in, 256);
    make_scale<<<2, 64>>>(0, g_in, b_in, 0, 128, 1.f / 32768.f);

    // --- axial attention along H ---
    gemm_k<1><<<dim3(256, 2), 256>>>(nullptr, 128);
    att_stats<<<512, 256>>>(256, 0);
    make_scale<<<1, 64>>>(256, ga_h, ba_h, 256, 24, 1.f / 2097152.f);
    att_pass2<<<dim3(512, 8), 256>>>(rel_h, 256, 304);
    make_scale<<<4, 64>>>(304, go_h, bo_h, 304, 256, 1.f / 32768.f);
    combine1<<<dim3(128, 8), 256>>>();

    // --- axial attention along W ---
    gemm_k<2><<<dim3(256, 2), 256>>>(nullptr, 128);
    att_stats<<<512, 256>>>(816, 1);
    make_scale<<<1, 64>>>(816, ga_w, ba_w, 816, 24, 1.f / 2097152.f);
    att_pass2<<<dim3(512, 8), 256>>>(rel_w, 816, 864);
    make_scale<<<4, 64>>>(864, go_w, bo_w, 864, 256, 1.f / 32768.f);

    // conv-out (fused combine2 at load, +stats) -> y2
    gemm_k<3><<<dim3(256, 2), 256>>>(nullptr, 128);
    make_scale<<<4, 64>>>(1376, g_out, b_out, 1376, 256, 1.f / 32768.f);

    final_k<<<32768, 256>>>(x_in, (float*)d_out);
}

// round 13
// speedup vs baseline: 1.2492x; 1.1064x over previous
#include <cuda_runtime.h>
#include <cuda_bf16.h>
#include <cstdint>

// ---------------------------------------------------------------------------
// Problem constants
//   B=8, C_IN=256, DIM=64, HEADS=8, D_IN=128, DKQ=8, DV=16, QKV=32
//   N = B*DIM*DIM = 32768 "pixels"; sequences: 512 of length 64
// ---------------------------------------------------------------------------
#define NT 32768
#define EPSV 1e-5f

__device__ float  g_y1[128 * NT];      // conv-in raw output, layout [c][b][w][h]
__device__ float  g_qkv[256 * NT];     // qkv, layout [o][bw][pos]
__device__ float  g_outatt[256 * NT];  // attention out (sve ch 0..127, sv 128..255)
__device__ float  g_x3[128 * NT];      // att1 combined (input to qkv2 GEMM)
__device__ float  g_y2[256 * NT];      // conv-out raw output [o][n1]
// stats offsets: convin @0(256) att1 @256(48) out1 @304(512) att2 @816(48)
//                out2 @864(512) convout @1376(512)
__device__ double g_st[1888];
__device__ float  g_sb[1888];

// Batch-aggregated correlations: [dir][which(q/k)][h][row(36 pairs + 8 sums)][d]
__device__ float g_C[2 * 2 * 8 * 44 * 64];   // 90112 floats

// Pre-converted weights: packed bf16x2 fragment-major hi/lo (m16n8k16 A frags)
__device__ uint32_t g_Ah[65536], g_Al[65536];

// Precomputed rel-embedding tables, double-buffered per direction
__device__ float g_Tq[2][8 * 64], g_Tk[2][8 * 64];
__device__ float g_Sq[2][36 * 64], g_Sk[2][36 * 64];

__device__ const int c_pi[36] = {0,0,0,0,0,0,0,0, 1,1,1,1,1,1,1, 2,2,2,2,2,2,
                                 3,3,3,3,3, 4,4,4,4, 5,5,5, 6,6, 7};
__device__ const int c_pj[36] = {0,1,2,3,4,5,6,7, 1,2,3,4,5,6,7, 2,3,4,5,6,7,
                                 3,4,5,6,7, 4,5,6,7, 5,6,7, 6,7, 7};

__global__ void zero_stats() {
    int i = blockIdx.x * 256 + threadIdx.x;
    if (i < 1888) g_st[i] = 0.0;
    else if (i - 1888 < 90112) g_C[i - 1888] = 0.f;
}

__global__ void make_scale(int stoff, const float* __restrict__ gamma,
                           const float* __restrict__ beta, int sboff, int C, float invN) {
    int t = blockIdx.x * 64 + threadIdx.x;
    if (t >= C) return;
    double mean = g_st[stoff + t] * (double)invN;
    double var  = g_st[stoff + C + t] * (double)invN - mean * mean;
    float s = gamma[t] * rsqrtf((float)var + EPSV);
    g_sb[sboff + t]     = s;
    g_sb[sboff + C + t] = beta[t] - (float)mean * s;
}

// ---------------------------------------------------------------------------
// 3xBF16 helpers
// ---------------------------------------------------------------------------
__device__ __forceinline__ uint32_t pack_bf16x2(float lo_elem, float hi_elem) {
    uint32_t p;
    asm("cvt.rn.bf16x2.f32 %0, %1, %2;" : "=r"(p) : "f"(hi_elem), "f"(lo_elem));
    return p;
}
__device__ __forceinline__ uint32_t split_pack(float x0, float x1, float& r0, float& r1) {
    uint32_t p = pack_bf16x2(x0, x1);
    __nv_bfloat162 b = *reinterpret_cast<__nv_bfloat162*>(&p);
    r0 = x0 - __bfloat162float(b.x);
    r1 = x1 - __bfloat162float(b.y);
    return p;
}

#define MMA_BF16(c, a0, a1, a2, a3, b0, b1)                                    \
    asm volatile(                                                              \
        "mma.sync.aligned.m16n8k16.row.col.f32.bf16.bf16.f32 "                 \
        "{%0,%1,%2,%3}, {%4,%5,%6,%7}, {%8,%9}, {%0,%1,%2,%3};"                \
        : "+f"(c[0]), "+f"(c[1]), "+f"(c[2]), "+f"(c[3])                       \
        : "r"(a0), "r"(a1), "r"(a2), "r"(a3), "r"(b0), "r"(b1))

#define CP_ASYNC16(dst_u32, src_ptr)                                           \
    asm volatile("cp.async.cg.shared.global [%0], [%1], 16;"                   \
                 :: "r"(dst_u32), "l"(src_ptr))
#define CP_COMMIT()  asm volatile("cp.async.commit_group;")
#define CP_WAIT0()   asm volatile("cp.async.wait_group 0;" ::: "memory")

// ---------------------------------------------------------------------------
// prep_A4: convert the 4 weight matrices to packed bf16x2 fragment-major hi/lo.
// ---------------------------------------------------------------------------
__global__ void __launch_bounds__(256) prep_A4(const float* __restrict__ w_in,
                                               const float* __restrict__ wqkv_h,
                                               const float* __restrict__ wqkv_w,
                                               const float* __restrict__ w_out) {
    int idx = blockIdx.x * 256 + threadIdx.x;   // 0..65535
    int mat = idx >> 14;
    int e2 = idx & 16383;
    const float* src = (mat == 0) ? w_in : (mat == 1) ? wqkv_h
                      : (mat == 2) ? wqkv_w : w_out;
    int M, K, m, kp;
    if (mat == 0) { M = 128; K = 256; m = e2 >> 7; kp = e2 & 127; }
    else          { M = 256; K = 128; m = e2 >> 6; kp = e2 & 63; }
    float x0 = src[m * K + kp * 2];
    float x1 = src[m * K + kp * 2 + 1];
    float r0, r1;
    uint32_t hi = split_pack(x0, x1, r0, r1);
    uint32_t lo = pack_bf16x2(r0, r1);
    int mp = m & 15, kpp = kp & 7;
    int frag = (kp >> 3) * (M >> 4) + (m >> 4);
    int lane = (mp & 7) * 4 + (kpp & 3);
    int reg  = ((kpp >> 2) & 1) * 2 + (mp >> 3);
    int word = (mat << 14) + frag * 128 + lane * 4 + reg;
    g_Ah[word] = hi;
    g_Al[word] = lo;
}

// ---------------------------------------------------------------------------
// Pipelined GEMM via 3xBF16 mma.sync m16n8k16, double-buffered, k-chunk 32.
//   Per chunk: 2 k-steps (ks 0/1), 96 MMAs/warp; one sync per chunk.
// Dynamic smem layout (u32 words):
//   Ah @0 (2x2048), Al @4096 (2x2048), Bs @8192 (2x4224), stats @16640 (512 f)
// ---------------------------------------------------------------------------
#define GEMM_SMEM_BYTES ((16640 + 512) * 4)

template <int MODE>
__device__ __forceinline__ float4 gemm_loadB(const float* __restrict__ Bext,
                                             int n0, int k, int nn) {
    if (MODE == 0) {
        return *(const float4*)&Bext[(n0 >> 12) * 1048576 + k * 4096 + (n0 & 4095) + nn];
    } else if (MODE == 3) {
        float4 a = *(const float4*)&g_outatt[k * NT + n0 + nn];
        float4 b = *(const float4*)&g_outatt[(128 + k) * NT + n0 + nn];
        float sA = g_sb[864 + k],       bA = g_sb[864 + 256 + k];
        float sB = g_sb[864 + 128 + k], bB = g_sb[864 + 256 + 128 + k];
        float4 v;
        v.x = fmaxf(a.x * sA + bA + b.x * sB + bB, 0.f);
        v.y = fmaxf(a.y * sA + bA + b.y * sB + bB, 0.f);
        v.z = fmaxf(a.z * sA + bA + b.z * sB + bB, 0.f);
        v.w = fmaxf(a.w * sA + bA + b.w * sB + bB, 0.f);
        return v;
    } else {
        const float* Bp = (MODE == 1) ? g_y1 : g_x3;
        float4 v = *(const float4*)&Bp[k * NT + n0 + nn];
        if (MODE == 1) {
            float s = g_sb[k], bi = g_sb[128 + k];
            v.x = fmaxf(fmaf(v.x, s, bi), 0.f);
            v.y = fmaxf(fmaf(v.y, s, bi), 0.f);
            v.z = fmaxf(fmaf(v.z, s, bi), 0.f);
            v.w = fmaxf(fmaf(v.w, s, bi), 0.f);
        }
        return v;
    }
}

template <int MODE>
__global__ void __launch_bounds__(256, 2) gemm_k(const float* __restrict__ Bext, int K) {
    constexpr int M     = (MODE == 0) ? 128 : 256;
    constexpr int WOFF4 = (MODE == 0) ? 0 : ((MODE == 1) ? 16384
                         : ((MODE == 2) ? 32768 : 49152));
    constexpr int KFR   = M >> 4;
    extern __shared__ uint32_t sm[];
    uint32_t* Ahb = sm;                        // 2 x 2048
    uint32_t* Alb = sm + 4096;                 // 2 x 2048
    uint32_t* Bsb = sm + 8192;                 // 2 x 4224
    float* ssum = (float*)(sm + 16640);
    float* ssq  = ssum + 128;
    const int n0 = blockIdx.x * 128;
    const int m0 = blockIdx.y * 128;
    const int tid = threadIdx.x;
    const int warp = tid >> 5, lane = tid & 31;
    const int mb4 = (warp & 1) * 4;
    const int nb4 = (warp >> 1) * 4;
    const int bn4 = lane * 4;

    float* Cp = (MODE == 0) ? g_y1 : ((MODE == 3) ? g_y2 : g_qkv);

    float acc[4][4][4];
#pragma unroll
    for (int mt = 0; mt < 4; mt++)
#pragma unroll
        for (int nt = 0; nt < 4; nt++)
#pragma unroll
            for (int c = 0; c < 4; c++) acc[mt][nt][c] = 0.f;

    float4 v[4];   // B rows: k0 + {2w, 2w+1, 16+2w, 16+2w+1}

    const int bword0 = (bn4 >> 3) * 132 + ((bn4 & 7) * 4 + (warp & 3)) * 4
                     + ((warp >> 2) & 1) * 2;

    auto stageB = [&](int stg) {
        uint32_t* Bs = Bsb + stg * 4224;
#pragma unroll
        for (int pr = 0; pr < 2; pr++) {
            const float* e0 = (const float*)&v[pr * 2];
            const float* e1 = (const float*)&v[pr * 2 + 1];
            int base = bword0 + pr * 2112;
#pragma unroll
            for (int j = 0; j < 4; j++) {
                float r0, r1;
                uint32_t hi = split_pack(e0[j], e1[j], r0, r1);
                uint32_t lo = pack_bf16x2(r0, r1);
                *(uint2*)&Bs[base + (j >> 1) * 132 * ((bn4 + j) >> 3 != (bn4 >> 3) ? 1 : 0)
                             + ((bn4 + j) >> 3) * 0 + 0 + // placeholder; recompute below
                             0] = make_uint2(hi, lo);
                (void)hi; (void)lo;
            }
        }
    };
    (void)stageB;  // replaced by explicit version below (lambda kept simple)

    auto stageB2 = [&](int stg) {
        uint32_t* Bs = Bsb + stg * 4224;
#pragma unroll
        for (int pr = 0; pr < 2; pr++) {
            const float* e0 = (const float*)&v[pr * 2];
            const float* e1 = (const float*)&v[pr * 2 + 1];
#pragma unroll
            for (int j = 0; j < 4; j++) {
                float r0, r1;
                uint32_t hi = split_pack(e0[j], e1[j], r0, r1);
                uint32_t lo = pack_bf16x2(r0, r1);
                int n = bn4 + j;
                int word = (n >> 3) * 132 + ((n & 7) * 4 + (warp & 3)) * 4
                         + ((warp >> 2) & 1) * 2 + pr * 2112;
                *(uint2*)&Bs[word] = make_uint2(hi, lo);
            }
        }
    };

    auto loadA = [&](int stg, int kgrp16, int half) {
        int sfrag = tid >> 5;
        int gw = WOFF4 + (kgrp16 * KFR + (m0 >> 4) + sfrag) * 128 + (tid & 31) * 4;
        int so = stg * 2048 + half * 1024 + sfrag * 128 + (tid & 31) * 4;
        CP_ASYNC16((uint32_t)__cvta_generic_to_shared(&Ahb[so]), &g_Ah[gw]);
        CP_ASYNC16((uint32_t)__cvta_generic_to_shared(&Alb[so]), &g_Al[gw]);
    };
    auto loadBv = [&](int k0) {
        v[0] = gemm_loadB<MODE>(Bext, n0, k0 + 2 * warp, bn4);
        v[1] = gemm_loadB<MODE>(Bext, n0, k0 + 2 * warp + 1, bn4);
        v[2] = gemm_loadB<MODE>(Bext, n0, k0 + 16 + 2 * warp, bn4);
        v[3] = gemm_loadB<MODE>(Bext, n0, k0 + 16 + 2 * warp + 1, bn4);
    };

    // --- prologue ---
    loadBv(0);
    loadA(0, 0, 0);
    loadA(0, 1, 1);
    CP_COMMIT();
    stageB2(0);
    CP_WAIT0();
    __syncthreads();

    const int nchunk = K >> 5;
    for (int c0 = 0; c0 < nchunk; c0++) {
        const int cur = c0 & 1, nxt = cur ^ 1;
        const bool more = (c0 + 1 < nchunk);

        if (more) {
            loadBv((c0 + 1) * 32);
            loadA(nxt, 2 * (c0 + 1), 0);
            loadA(nxt, 2 * (c0 + 1) + 1, 1);
            CP_COMMIT();
        }

        // ---- compute: 2 k-steps x 48 MMAs ----
        const uint32_t* Ah = Ahb + cur * 2048;
        const uint32_t* Al = Alb + cur * 2048;
        const uint32_t* Bs = Bsb + cur * 4224;
#pragma unroll
        for (int ks = 0; ks < 2; ks++) {
            uint4 bq[4];
#pragma unroll
            for (int nt = 0; nt < 4; nt++)
                bq[nt] = *(const uint4*)&Bs[(ks * 16 + nb4 + nt) * 132 + lane * 4];
#pragma unroll
            for (int mt = 0; mt < 4; mt++) {
                uint4 ah = *(const uint4*)&Ah[ks * 1024 + (mb4 + mt) * 128 + lane * 4];
                uint4 al = *(const uint4*)&Al[ks * 1024 + (mb4 + mt) * 128 + lane * 4];
#pragma unroll
                for (int nt = 0; nt < 4; nt++) {
                    MMA_BF16(acc[mt][nt], ah.x, ah.y, ah.z, ah.w, bq[nt].x, bq[nt].z);
                    MMA_BF16(acc[mt][nt], al.x, al.y, al.z, al.w, bq[nt].x, bq[nt].z);
                    MMA_BF16(acc[mt][nt], ah.x, ah.y, ah.z, ah.w, bq[nt].y, bq[nt].w);
                }
            }
        }

        if (more) {
            stageB2(nxt);
            CP_WAIT0();
            __syncthreads();
        }
    }
    __syncthreads();

    if (MODE == 0 || MODE == 3) {
        for (int t = tid; t < 128; t += 256) { ssum[t] = 0.f; ssq[t] = 0.f; }
        __syncthreads();
    }

    const int mb = (warp & 1) * 64, nb = (warp >> 1) * 32;
    const int lqe = lane & 3, lre = lane >> 2;
    if (MODE == 0) {
        const int bb = n0 >> 12, hw0 = n0 & 4095;
#pragma unroll
        for (int mt = 0; mt < 4; mt++) {
#pragma unroll
            for (int half = 0; half < 2; half++) {
                int o = mb + mt * 16 + lre + half * 8;  // m0 == 0
                float rs = 0.f, rq = 0.f;
#pragma unroll
                for (int nt = 0; nt < 4; nt++) {
#pragma unroll
                    for (int cc = 0; cc < 2; cc++) {
                        int hw = hw0 + nb + nt * 8 + 2 * lqe + cc;
                        float vv = acc[mt][nt][half * 2 + cc];
                        Cp[o * NT + bb * 4096 + (hw & 63) * 64 + (hw >> 6)] = vv;
                        rs += vv; rq += vv * vv;
                    }
                }
                atomicAdd(&ssum[o], rs);
                atomicAdd(&ssq[o], rq);
            }
        }
    } else {
#pragma unroll
        for (int mt = 0; mt < 4; mt++) {
#pragma unroll
            for (int half = 0; half < 2; half++) {
                int o = m0 + mb + mt * 16 + lre + half * 8;
                float rs = 0.f, rq = 0.f;
#pragma unroll
                for (int nt = 0; nt < 4; nt++) {
                    float2 v2 = make_float2(acc[mt][nt][half * 2], acc[mt][nt][half * 2 + 1]);
                    *(float2*)&Cp[o * NT + n0 + nb + nt * 8 + 2 * lqe] = v2;
                    if (MODE == 3) { rs += v2.x + v2.y; rq += v2.x * v2.x + v2.y * v2.y; }
                }
                if (MODE == 3) {
                    atomicAdd(&ssum[o - m0], rs);
                    atomicAdd(&ssq[o - m0], rq);
                }
            }
        }
    }

    if (MODE == 0 || MODE == 3) {
        __syncthreads();
        const int base = (MODE == 0) ? 0 : 1376;
        const int Csz  = (MODE == 0) ? 128 : 256;
        if (tid < 128) {
            atomicAdd(&g_st[base + m0 + tid], (double)ssum[tid]);
            atomicAdd(&g_st[base + Csz + m0 + tid], (double)ssq[tid]);
        }
    }
}

// ---------------------------------------------------------------------------
// prep_S: precompute sliding-window tables of the rel embedding.
// ---------------------------------------------------------------------------
__global__ void __launch_bounds__(256) prep_S(const float* __restrict__ rel_h,
                                              const float* __restrict__ rel_w) {
    const int dir = blockIdx.y;
    const float* rel = dir ? rel_w : rel_h;
    __shared__ float r[16][127];
    for (int t = threadIdx.x; t < 16 * 127; t += 256) r[t / 127][t % 127] = rel[t];
    __syncthreads();
    const int g0 = blockIdx.x * 256 + threadIdx.x;
    const int gs = gridDim.x * 256;
    for (int t = g0; t < 1024; t += gs) {
        int which = t >> 9, i = (t >> 6) & 7, d = t & 63;
        const float* rr = r[which * 8 + i];
        float s = 0.f;
        for (int u = 0; u < 64; u++) s += rr[d + u];
        (which ? g_Tk[dir] : g_Tq[dir])[i * 64 + d] = s;
    }
    for (int t = g0; t < 4608; t += gs) {
        int which = t / 2304, rem = t % 2304, p = rem >> 6, d = rem & 63;
        const float* a = r[which * 8 + c_pi[p]];
        const float* b = r[which * 8 + c_pj[p]];
        float s = 0.f;
        for (int u = 0; u < 64; u++) s = fmaf(a[d + u], b[d + u], s);
        (which ? g_Sk[dir] : g_Sq[dir])[p * 64 + d] = s;
    }
}

// ---------------------------------------------------------------------------
// att_corr: batch-aggregated correlations C[which][h][p][d] = sum_bw x_i x_i'
// and channel sums (rows 36..43).  grid (8 bw-slices, 8 h, 2 which).
// ---------------------------------------------------------------------------
__global__ void __launch_bounds__(256) att_corr(int dir) {
    const int h = blockIdx.y, which = blockIdx.z;
    const int bw0 = blockIdx.x * 64;
    const int tid = threadIdx.x;
    __shared__ float sC[8 * 16 * 64];   // [i][bwl][d]
    float acc[11];
#pragma unroll
    for (int p = 0; p < 11; p++) acc[p] = 0.f;

    for (int sub = 0; sub < 4; sub++) {
        __syncthreads();
        const int bwb = bw0 + sub * 16;
        for (int t = tid; t < 2048; t += 256) {
            int i = t >> 8, rem = t & 255;
            float4 vv = *(const float4*)&g_qkv[(which * 64 + i * 8 + h) * NT
                                               + bwb * 64 + rem * 4];
            *(float4*)&sC[i * 1024 + rem * 4] = vv;
        }
        __syncthreads();
#pragma unroll
        for (int pass = 0; pass < 11; pass++) {
            int op = pass * 256 + tid;
            int row = op >> 6, d = op & 63;
            float a = acc[pass];
            if (row < 36) {
                const float* p1 = &sC[c_pi[row] * 1024 + d];
                const float* p2 = &sC[c_pj[row] * 1024 + d];
#pragma unroll
                for (int b = 0; b < 16; b++) a = fmaf(p1[b * 64], p2[b * 64], a);
            } else {
                const float* p1 = &sC[(row - 36) * 1024 + d];
#pragma unroll
                for (int b = 0; b < 16; b++) a += p1[b * 64];
            }
            acc[pass] = a;
        }
    }
#pragma unroll
    for (int pass = 0; pass < 11; pass++) {
        int op = pass * 256 + tid;
        atomicAdd(&g_C[(((dir * 2 + which) * 8 + h) * 44) * 64 + op], acc[pass]);
    }
}

// ---------------------------------------------------------------------------
// att_wsum: fold aggregated correlations with S/T tables into the qr/kr stats.
// One block; thread = (h, lane).
// ---------------------------------------------------------------------------
__global__ void __launch_bounds__(256) att_wsum(int dir, int stoff) {
    const int tid = threadIdx.x;
    const int h = tid >> 5, lane = tid & 31;
    const float* Cq = &g_C[((dir * 2 + 0) * 8 + h) * 44 * 64];
    const float* Ck = &g_C[((dir * 2 + 1) * 8 + h) * 44 * 64];
    float qs = 0.f, ks = 0.f, wq = 0.f, wk = 0.f;
    for (int i = 0; i < 8; i++)
        for (int d = lane; d < 64; d += 32) {
            qs = fmaf(Cq[(36 + i) * 64 + d], g_Tq[dir][i * 64 + d], qs);
            ks = fmaf(Ck[(36 + i) * 64 + d], g_Tk[dir][i * 64 + d], ks);
        }
    for (int p = 0; p < 36; p++) {
        float m = (c_pi[p] == c_pj[p]) ? 1.f : 2.f;
        float aq = 0.f, ak = 0.f;
        for (int d = lane; d < 64; d += 32) {
            aq = fmaf(Cq[p * 64 + d], g_Sq[dir][p * 64 + d], aq);
            ak = fmaf(Ck[p * 64 + d], g_Sk[dir][p * 64 + d], ak);
        }
        wq = fmaf(m, aq, wq);
        wk = fmaf(m, ak, wk);
    }
#pragma unroll
    for (int off = 16; off; off >>= 1) {
        qs += __shfl_xor_sync(~0u, qs, off);
        ks += __shfl_xor_sync(~0u, ks, off);
        wq += __shfl_xor_sync(~0u, wq, off);
        wk += __shfl_xor_sync(~0u, wk, off);
    }
    if (lane == 0) {
        g_st[stoff + h * 3 + 0] = (double)qs;
        g_st[stoff + h * 3 + 1] = (double)ks;
        g_st[stoff + 24 + h * 3 + 0] = (double)wq;
        g_st[stoff + 24 + h * 3 + 1] = (double)wk;
    }
}

// ---------------------------------------------------------------------------
// att_stats: per-bw stats that cannot be linearized: sum dots & sumsq dots.
// ---------------------------------------------------------------------------
__global__ void __launch_bounds__(256) att_stats(int stoff) {
    const int bw = blockIdx.x, tid = threadIdx.x;
    __shared__ float qT[8][512];   // [h][d*8 + i]
    __shared__ float kT[8][512];
    __shared__ float rsq[8][8], rsk[8][8];

    for (int t = tid; t < 8192; t += 256) {
        int which = t >> 12, o = (t >> 6) & 63, d = t & 63;
        float v = g_qkv[(which * 64 + o) * NT + bw * 64 + d];
        int h = o & 7, i = o >> 3;
        if (which == 0) qT[h][d * 8 + i] = v; else kT[h][d * 8 + i] = v;
    }
    __syncthreads();

    const int h = tid >> 5, lane = tid & 31;
    if (lane < 8) {
        float s = 0.f;
        for (int d = 0; d < 64; d++) s += qT[h][d * 8 + lane];
        rsq[h][lane] = s;
    } else if (lane < 16) {
        int i = lane - 8; float s = 0.f;
        for (int d = 0; d < 64; d++) s += kT[h][d * 8 + i];
        rsk[h][i] = s;
    }

    float dsq = 0.f;
    for (int p = lane; p < 36; p += 32) {
        int i = c_pi[p], i2 = c_pj[p];
        float m = (i == i2) ? 1.f : 2.f;
        float gq = 0.f, gk = 0.f;
        for (int d = 0; d < 64; d++) {
            gq = fmaf(qT[h][d * 8 + i], qT[h][d * 8 + i2], gq);
            gk = fmaf(kT[h][d * 8 + i], kT[h][d * 8 + i2], gk);
        }
        dsq = fmaf(m * gq, gk, dsq);
    }
#pragma unroll
    for (int off = 16; off; off >>= 1)
        dsq += __shfl_xor_sync(~0u, dsq, off);
    __syncwarp();
    if (lane == 0) {
        float ds = 0.f;
#pragma unroll
        for (int i = 0; i < 8; i++) ds = fmaf(rsq[h][i], rsk[h][i], ds);
        atomicAdd(&g_st[stoff + h * 3 + 2], (double)ds);
        atomicAdd(&g_st[stoff + 24 + h * 3 + 2], (double)dsq);
    }
}

// ---------------------------------------------------------------------------
// att_pass2: logits (BN applied) -> softmax -> sv & sve.  Conflict-free.
// ---------------------------------------------------------------------------
__global__ void __launch_bounds__(256) att_pass2(const float* __restrict__ rel,
                                                 int sba, int sto) {
    const int bw = blockIdx.x, h = blockIdx.y, tid = threadIdx.x;
    const int warp = tid >> 5, lane = tid & 31;
    __shared__ float sq[8][65], sk[8][65], svv[16][65];
    __shared__ float srel[32][129];
    __shared__ float sat[64][65];

#pragma unroll
    for (int r = 0; r < 8; r++) {
        int t = tid + r * 256;
        int o = t >> 6, d = t & 63;
        float v = g_qkv[(o * 8 + h) * NT + bw * 64 + d];
        if (o < 8) sq[o][d] = v;
        else if (o < 16) sk[o - 8][d] = v;
        else svv[o - 16][d] = v;
    }
    for (int t = tid; t < 32 * 127; t += 256) srel[t / 127][t % 127] = rel[t];
    const float s0 = g_sb[sba + h * 3], s1v = g_sb[sba + h * 3 + 1], s2v = g_sb[sba + h * 3 + 2];
    const float bsum = g_sb[sba + 24 + h * 3] + g_sb[sba + 24 + h * 3 + 1]
                     + g_sb[sba + 24 + h * 3 + 2];
    __syncthreads();

    {   // Phase A
        float kk0[8], kk1[8];
#pragma unroll
        for (int i = 0; i < 8; i++) {
            kk0[i] = sk[i][lane];
            kk1[i] = sk[i][lane + 32];
        }
        const int dbase = warp * 8;
#pragma unroll
        for (int r = 0; r < 8; r++) {
            const int d = dbase + r;
            const int m0 = d - lane + 63;
            float qr0 = 0, kr0 = 0, dt0 = 0, qr1 = 0, kr1 = 0, dt1 = 0;
#pragma unroll
            for (int i = 0; i < 8; i++) {
                float qi  = sq[i][d];
                float kdi = sk[i][d];
                float rq0 = srel[i][m0],     rq1 = srel[i][m0 - 32];
                float rk0 = srel[8 + i][m0], rk1 = srel[8 + i][m0 - 32];
                qr0 = fmaf(qi, rq0, qr0);   qr1 = fmaf(qi, rq1, qr1);
                kr0 = fmaf(kdi, rk0, kr0);  kr1 = fmaf(kdi, rk1, kr1);
                dt0 = fmaf(qi, kk0[i], dt0); dt1 = fmaf(qi, kk1[i], dt1);
            }
            float l0 = qr0 * s0 + kr0 * s1v + dt0 * s2v + bsum;
            float l1 = qr1 * s0 + kr1 * s1v + dt1 * s2v + bsum;
            float mx = fmaxf(l0, l1);
#pragma unroll
            for (int off = 16; off; off >>= 1)
                mx = fmaxf(mx, __shfl_xor_sync(~0u, mx, off));
            float e0 = __expf(l0 - mx), e1 = __expf(l1 - mx);
            float se = e0 + e1;
#pragma unroll
            for (int off = 16; off; off >>= 1)
                se += __shfl_xor_sync(~0u, se, off);
            float inv = 1.f / se;
            sat[d][lane]      = e0 * inv;
            sat[d][lane + 32] = e1 * inv;
        }
    }
    __syncthreads();

    {   // Phase B
        const int i0 = warp * 2, i1 = i0 + 1;
        const int da = lane, db = lane + 32;
        float av0a = 0, av0b = 0, av1a = 0, av1b = 0;
        float ae0a = 0, ae0b = 0, ae1a = 0, ae1b = 0;
        const float* r0 = &srel[16 + i0][0];
        const float* r1 = &srel[16 + i1][0];
#pragma unroll 4
        for (int j = 0; j < 64; j++) {
            float Aa = sat[da][j];
            float Ab = sat[db][j];
            float v0 = svv[i0][j], v1 = svv[i1][j];
            float r0a = r0[da - j + 63], r0b = r0[db - j + 63];
            float r1a = r1[da - j + 63], r1b = r1[db - j + 63];
            av0a = fmaf(Aa, v0, av0a);  av0b = fmaf(Ab, v0, av0b);
            av1a = fmaf(Aa, v1, av1a);  av1b = fmaf(Ab, v1, av1b);
            ae0a = fmaf(Aa, r0a, ae0a); ae0b = fmaf(Ab, r0b, ae0b);
            ae1a = fmaf(Aa, r1a, ae1a); ae1b = fmaf(Ab, r1b, ae1b);
        }
        const int ch0 = h * 16 + i0, ch1 = h * 16 + i1;
        g_outatt[ch0 * NT + bw * 64 + da] = ae0a;
        g_outatt[ch0 * NT + bw * 64 + db] = ae0b;
        g_outatt[ch1 * NT + bw * 64 + da] = ae1a;
        g_outatt[ch1 * NT + bw * 64 + db] = ae1b;
        g_outatt[(128 + ch0) * NT + bw * 64 + da] = av0a;
        g_outatt[(128 + ch0) * NT + bw * 64 + db] = av0b;
        g_outatt[(128 + ch1) * NT + bw * 64 + da] = av1a;
        g_outatt[(128 + ch1) * NT + bw * 64 + db] = av1b;

        float se0 = ae0a + ae0b, qe0 = ae0a * ae0a + ae0b * ae0b;
        float se1 = ae1a + ae1b, qe1 = ae1a * ae1a + ae1b * ae1b;
        float sv0 = av0a + av0b, qv0 = av0a * av0a + av0b * av0b;
        float sv1 = av1a + av1b, qv1 = av1a * av1a + av1b * av1b;
#pragma unroll
        for (int off = 16; off; off >>= 1) {
            se0 += __shfl_xor_sync(~0u, se0, off); qe0 += __shfl_xor_sync(~0u, qe0, off);
            se1 += __shfl_xor_sync(~0u, se1, off); qe1 += __shfl_xor_sync(~0u, qe1, off);
            sv0 += __shfl_xor_sync(~0u, sv0, off); qv0 += __shfl_xor_sync(~0u, qv0, off);
            sv1 += __shfl_xor_sync(~0u, sv1, off); qv1 += __shfl_xor_sync(~0u, qv1, off);
        }
        if (lane == 0) {
            atomicAdd(&g_st[sto + ch0], (double)se0);
            atomicAdd(&g_st[sto + ch1], (double)se1);
            atomicAdd(&g_st[sto + 256 + ch0], (double)qe0);
            atomicAdd(&g_st[sto + 256 + ch1], (double)qe1);
            atomicAdd(&g_st[sto + 128 + ch0], (double)sv0);
            atomicAdd(&g_st[sto + 128 + ch1], (double)sv1);
            atomicAdd(&g_st[sto + 256 + 128 + ch0], (double)qv0);
            atomicAdd(&g_st[sto + 256 + 128 + ch1], (double)qv1);
        }
    }
}

// combine att1: x3[c][b][h][w] = bn(sve) + bn(sv), with h<->w transpose
__global__ void __launch_bounds__(256) combine1() {
    const int c = blockIdx.x, b = blockIdx.y, tid = threadIdx.x;
    __shared__ float tile[64][65];
    const float sA = g_sb[304 + c],        bA = g_sb[304 + 256 + c];
    const float sB = g_sb[304 + c + 128],  bB = g_sb[304 + 256 + c + 128];
    const float* pA = g_outatt + c * NT + b * 4096;
    const float* pB = g_outatt + (c + 128) * NT + b * 4096;
    for (int t = tid; t < 4096; t += 256)
        tile[t >> 6][t & 63] = pA[t] * sA + bA + pB[t] * sB + bB;
    __syncthreads();
    float* q = g_x3 + c * NT + b * 4096;
    for (int t = tid; t < 4096; t += 256)
        q[t] = tile[t & 63][t >> 6];
}

// final: out = relu(bn(conv_out) + x_in)
__global__ void __launch_bounds__(256) final_k(const float* __restrict__ x_in,
                                               float* __restrict__ out) {
    int idx = blockIdx.x * 256 + threadIdx.x;
    int o = idx >> 15, m = idx & (NT - 1);
    int b = m >> 12, hw = m & 4095;
    float v = g_y2[idx] * g_sb[1376 + o] + g_sb[1376 + 256 + o];
    int oidx = (b * 256 + o) * 4096 + hw;
    v += x_in[oidx];
    out[oidx] = fmaxf(v, 0.f);
}

// ---------------------------------------------------------------------------
extern "C" void kernel_launch(void* const* d_in, const int* in_sizes, int n_in,
                              void* d_out, int out_size) {
    (void)in_sizes; (void)n_in; (void)out_size;
    const float* x_in   = (const float*)d_in[0];
    const float* w_in   = (const float*)d_in[1];
    const float* g_in   = (const float*)d_in[2];
    const float* b_in   = (const float*)d_in[3];
    const float* w_out  = (const float*)d_in[4];
    const float* g_out  = (const float*)d_in[5];
    const float* b_out  = (const float*)d_in[6];
    const float* wqkv_h = (const float*)d_in[7];
    const float* rel_h  = (const float*)d_in[8];
    const float* ga_h   = (const float*)d_in[9];
    const float* ba_h   = (const float*)d_in[10];
    const float* go_h   = (const float*)d_in[11];
    const float* bo_h   = (const float*)d_in[12];
    const float* wqkv_w = (const float*)d_in[13];
    const float* rel_w  = (const float*)d_in[14];
    const float* ga_w   = (const float*)d_in[15];
    const float* ba_w   = (const float*)d_in[16];
    const float* go_w   = (const float*)d_in[17];
    const float* bo_w   = (const float*)d_in[18];

    cudaFuncSetAttribute(gemm_k<0>, cudaFuncAttributeMaxDynamicSharedMemorySize, GEMM_SMEM_BYTES);
    cudaFuncSetAttribute(gemm_k<1>, cudaFuncAttributeMaxDynamicSharedMemorySize, GEMM_SMEM_BYTES);
    cudaFuncSetAttribute(gemm_k<2>, cudaFuncAttributeMaxDynamicSharedMemorySize, GEMM_SMEM_BYTES);
    cudaFuncSetAttribute(gemm_k<3>, cudaFuncAttributeMaxDynamicSharedMemorySize, GEMM_SMEM_BYTES);

    zero_stats<<<360, 256>>>();                                 // 0
    prep_S<<<dim3(12, 2), 256>>>(rel_h, rel_w);                 // 1
    prep_A4<<<256, 256>>>(w_in, wqkv_h, wqkv_w, w_out);         // 2

    // conv-in (+stats) -> y1                                   // 3 (profiled)
    gemm_k<0><<<dim3(256, 1), 256, GEMM_SMEM_BYTES>>>(x_in, 256);
    make_scale<<<2, 64>>>(0, g_in, b_in, 0, 128, 1.f / 32768.f);

    // --- axial attention along H ---
    gemm_k<1><<<dim3(256, 2), 256, GEMM_SMEM_BYTES>>>(nullptr, 128);
    att_corr<<<dim3(8, 8, 2), 256>>>(0);
    att_stats<<<512, 256>>>(256);
    att_wsum<<<1, 256>>>(0, 256);
    make_scale<<<1, 64>>>(256, ga_h, ba_h, 256, 24, 1.f / 2097152.f);
    att_pass2<<<dim3(512, 8), 256>>>(rel_h, 256, 304);
    make_scale<<<4, 64>>>(304, go_h, bo_h, 304, 256, 1.f / 32768.f);
    combine1<<<dim3(128, 8), 256>>>();

    // --- axial attention along W ---
    gemm_k<2><<<dim3(256, 2), 256, GEMM_SMEM_BYTES>>>(nullptr, 128);
    att_corr<<<dim3(8, 8, 2), 256>>>(1);
    att_stats<<<512, 256>>>(816);
    att_wsum<<<1, 256>>>(1, 816);
    make_scale<<<1, 64>>>(816, ga_w, ba_w, 816, 24, 1.f / 2097152.f);
    att_pass2<<<dim3(512, 8), 256>>>(rel_w, 816, 864);
    make_scale<<<4, 64>>>(864, go_w, bo_w, 864, 256, 1.f / 32768.f);

    // conv-out (fused combine2 at load, +stats) -> y2
    gemm_k<3><<<dim3(256, 2), 256, GEMM_SMEM_BYTES>>>(nullptr, 128);
    make_scale<<<4, 64>>>(1376, g_out, b_out, 1376, 256, 1.f / 32768.f);

    final_k<<<32768, 256>>>(x_in, (float*)d_out);
}